// round 1
// baseline (speedup 1.0000x reference)
#include <cuda_runtime.h>
#include <math.h>

// Problem constants
#define BB   256   // batch
#define LL   32    // seq len
#define HH   512   // hidden
#define DD   512   // input dim
#define NS   64    // slot pool per batch (32 leaves + up to 31 composed)
#define G5   2560  // 5*H
// combined [Wl;Wr] output width = 2*G5 = 5120

// ---------------- static device scratch (no allocations allowed) ----------------
__device__ float g_h [BB * NS * HH];            // slot h vectors
__device__ float g_c [BB * NS * HH];            // slot c vectors
__device__ float g_ch[BB * NS * HH];            // candidate h, keyed by left slot id
__device__ float g_cc[BB * NS * HH];            // candidate c
__device__ float g_vl[(size_t)BB * NS * G5];    // Wl @ h_slot
__device__ float g_vr[(size_t)BB * NS * G5];    // Wr @ h_slot
__device__ float g_clog[BB * NS];               // candidate logits, keyed by left slot id
__device__ int   g_seq [BB * 32];               // current sequence: slot ids
__device__ int4  g_jobs[BB * 2];                // per-step recompute jobs {key, L, R, valid}

// ---------------- init: seq[b][j] = j ----------------
__global__ void init_k()
{
    int idx = blockIdx.x * blockDim.x + threadIdx.x;
    if (idx < BB * 32) g_seq[idx] = idx & 31;
}

// ---------------- generic SGEMM: C[M,N] = A[M,K=512] * W[N,K=512]^T ----------------
// mode 0: word projection  A=x rows,        W=W_word (1024 rows), out -> g_h/g_c leaves (+b_word)
// mode 1: leaf transforms  A=leaf h rows,   W=[Wl;Wr] (5120),     out -> g_vl/g_vr leaves
// mode 2: step transform   A=new-slot rows, W=[Wl;Wr] (5120),     out -> g_vl/g_vr slot 32+step
// Tile: BM=64, BN=128, BK=16, 256 threads, 4x8 microtile.
__global__ __launch_bounds__(256) void gemm_k(
    int mode, int step,
    const float* __restrict__ x, const float* __restrict__ W_word,
    const float* __restrict__ b_word, const float* __restrict__ W_comp)
{
    __shared__ __align__(16) float As[16][68];
    __shared__ __align__(16) float Bs[16][132];

    int tid = threadIdx.x;
    int ty = tid >> 4, tx = tid & 15;
    int m0 = blockIdx.x * 64;
    int n0 = blockIdx.y * 128;

    // A-tile load assignment: 1 float4 per thread
    int mI  = tid >> 2;         // 0..63
    int kqA = (tid & 3) * 4;    // 0,4,8,12
    {
    }
    const float* aptr;
    {
        int m = m0 + mI;
        if (mode == 0)      aptr = x + (size_t)m * DD;
        else if (mode == 1) aptr = g_h + (size_t)((m >> 5) * NS + (m & 31)) * HH;
        else                aptr = g_h + (size_t)(m * NS + 32 + step) * HH;
        aptr += kqA;
    }

    // B-tile load assignment: 2 float4 per thread
    const float* bptr[2];
    int kqB[2], nI[2];
#pragma unroll
    for (int r = 0; r < 2; r++) {
        int q = tid + r * 256;
        nI[r]  = q >> 2;            // 0..127
        kqB[r] = (q & 3) * 4;
        int n = n0 + nI[r];
        const float* wp;
        if (mode == 0) wp = W_word + (size_t)n * DD;
        else wp = (n < G5) ? (W_comp + (size_t)n * 1024)
                           : (W_comp + (size_t)(n - G5) * 1024 + 512);
        bptr[r] = wp + kqB[r];
    }

    float acc[4][8];
#pragma unroll
    for (int i = 0; i < 4; i++)
#pragma unroll
        for (int j = 0; j < 8; j++) acc[i][j] = 0.f;

    for (int k0 = 0; k0 < 512; k0 += 16) {
        float4 av = *reinterpret_cast<const float4*>(aptr + k0);
        As[kqA + 0][mI] = av.x;
        As[kqA + 1][mI] = av.y;
        As[kqA + 2][mI] = av.z;
        As[kqA + 3][mI] = av.w;
#pragma unroll
        for (int r = 0; r < 2; r++) {
            float4 bv = *reinterpret_cast<const float4*>(bptr[r] + k0);
            Bs[kqB[r] + 0][nI[r]] = bv.x;
            Bs[kqB[r] + 1][nI[r]] = bv.y;
            Bs[kqB[r] + 2][nI[r]] = bv.z;
            Bs[kqB[r] + 3][nI[r]] = bv.w;
        }
        __syncthreads();
#pragma unroll
        for (int kk = 0; kk < 16; kk++) {
            float a[4], b[8];
            *reinterpret_cast<float4*>(a)     = *reinterpret_cast<const float4*>(&As[kk][ty * 4]);
            *reinterpret_cast<float4*>(b)     = *reinterpret_cast<const float4*>(&Bs[kk][tx * 8]);
            *reinterpret_cast<float4*>(b + 4) = *reinterpret_cast<const float4*>(&Bs[kk][tx * 8 + 4]);
#pragma unroll
            for (int i = 0; i < 4; i++)
#pragma unroll
                for (int j = 0; j < 8; j++)
                    acc[i][j] = fmaf(a[i], b[j], acc[i][j]);
        }
        __syncthreads();
    }

    // epilogue
#pragma unroll
    for (int i = 0; i < 4; i++) {
        int m = m0 + ty * 4 + i;
#pragma unroll
        for (int j = 0; j < 8; j++) {
            int n = n0 + tx * 8 + j;
            float v = acc[i][j];
            if (mode == 0) {
                v += b_word[n];
                int bb = m >> 5, l = m & 31;
                if (n < HH) g_h[(size_t)(bb * NS + l) * HH + n] = v;
                else        g_c[(size_t)(bb * NS + l) * HH + (n - HH)] = v;
            } else {
                int bb, slot;
                if (mode == 1) { bb = m >> 5; slot = m & 31; }
                else           { bb = m;      slot = 32 + step; }
                size_t base = (size_t)(bb * NS + slot) * G5;
                if (n < G5) g_vl[base + n] = v;
                else        g_vr[base + (n - G5)] = v;
            }
        }
    }
}

// ---------------- pair gates + logit ----------------
__device__ __forceinline__ float sigf(float x) { return 1.f / (1.f + expf(-x)); }

__global__ __launch_bounds__(128) void pair_k(
    const float* __restrict__ b_comp, const float* __restrict__ cq, int initMode)
{
    int blk = blockIdx.x;
    int b, key, Ls, Rs;
    if (initMode) {
        b = blk / 31;
        int j = blk - b * 31;
        key = j; Ls = j; Rs = j + 1;
    } else {
        b = blk >> 1;
        int4 job = g_jobs[blk];
        if (!job.w) return;
        key = job.x; Ls = job.y; Rs = job.z;
    }
    int t = threadIdx.x;  // float4 index over H: 0..127

    const float4* vl = reinterpret_cast<const float4*>(g_vl + (size_t)(b * NS + Ls) * G5);
    const float4* vr = reinterpret_cast<const float4*>(g_vr + (size_t)(b * NS + Rs) * G5);
    const float4* bc = reinterpret_cast<const float4*>(b_comp);
    const float4* cl4 = reinterpret_cast<const float4*>(g_c + (size_t)(b * NS + Ls) * HH);
    const float4* cr4 = reinterpret_cast<const float4*>(g_c + (size_t)(b * NS + Rs) * HH);
    const float4* q4  = reinterpret_cast<const float4*>(cq);

    float vi[4], vfl[4], vfr[4], vu[4], vo[4];
    {
        float* dsts[5] = {vi, vfl, vfr, vu, vo};
#pragma unroll
        for (int g = 0; g < 5; g++) {
            float4 a  = vl[g * 128 + t];
            float4 bb = vr[g * 128 + t];
            float4 c  = bc[g * 128 + t];
            dsts[g][0] = a.x + bb.x + c.x;
            dsts[g][1] = a.y + bb.y + c.y;
            dsts[g][2] = a.z + bb.z + c.z;
            dsts[g][3] = a.w + bb.w + c.w;
        }
    }
    float4 cl = cl4[t], cr = cr4[t], qv = q4[t];
    float clv[4] = {cl.x, cl.y, cl.z, cl.w};
    float crv[4] = {cr.x, cr.y, cr.z, cr.w};
    float qa[4]  = {qv.x, qv.y, qv.z, qv.w};

    float hh[4], cc[4];
    float part = 0.f;
#pragma unroll
    for (int e = 0; e < 4; e++) {
        float c = clv[e] * sigf(vfl[e] + 1.f)
                + crv[e] * sigf(vfr[e] + 1.f)
                + tanhf(vu[e]) * sigf(vi[e]);
        float h = sigf(vo[e]) * tanhf(c);
        cc[e] = c; hh[e] = h;
        part = fmaf(qa[e], h, part);
    }
    reinterpret_cast<float4*>(g_ch + (size_t)(b * NS + key) * HH)[t] = make_float4(hh[0], hh[1], hh[2], hh[3]);
    reinterpret_cast<float4*>(g_cc + (size_t)(b * NS + key) * HH)[t] = make_float4(cc[0], cc[1], cc[2], cc[3]);

#pragma unroll
    for (int o = 16; o; o >>= 1) part += __shfl_xor_sync(0xffffffffu, part, o);
    __shared__ float ws[4];
    if ((t & 31) == 0) ws[t >> 5] = part;
    __syncthreads();
    if (t == 0) {
        float tot = ws[0] + ws[1] + ws[2] + ws[3];
        g_clog[b * NS + key] = tot * 0.044194173824159216f;  // 1/sqrt(512)
    }
}

// ---------------- per-step planner: mask, argmax, merge, emit jobs ----------------
__global__ void plan_k(const int* __restrict__ length, int i)
{
    int b = blockIdx.x;
    int lane = threadIdx.x;  // 32 lanes
    int ell = length[b];
    bool done = (i + 1 < ell);
    if (!done) {
        // sequence truncates implicitly (cur = 32 - i tracked by step index)
        if (lane == 0) {
            g_jobs[b * 2]     = make_int4(0, 0, 0, 0);
            g_jobs[b * 2 + 1] = make_int4(0, 0, 0, 0);
        }
        return;
    }
    int npairs = 31 - i;
    int seqv = g_seq[b * 32 + lane];
    bool valid = (lane < ell - i - 1);  // reference mask: (i+1+j) < length
    float lg = valid ? g_clog[b * NS + seqv] : -1e9f;

    float mx = lg;
#pragma unroll
    for (int o = 16; o; o >>= 1) mx = fmaxf(mx, __shfl_xor_sync(0xffffffffu, mx, o));
    unsigned bal = __ballot_sync(0xffffffffu, lg == mx);
    int k = __ffs(bal) - 1;  // first-max, matches jnp.argmax

    int s = 32 + i;  // new slot id
    int sk   = __shfl_sync(0xffffffffu, seqv, k);
    int skm1 = __shfl_sync(0xffffffffu, seqv, (k > 0) ? (k - 1) : 0);
    int skp2 = __shfl_sync(0xffffffffu, seqv, (k + 2 < 32) ? (k + 2) : 31);

    // selected candidate becomes the new node
    {
        const float4* sh = reinterpret_cast<const float4*>(g_ch + (size_t)(b * NS + sk) * HH);
        const float4* sc = reinterpret_cast<const float4*>(g_cc + (size_t)(b * NS + sk) * HH);
        float4* dh = reinterpret_cast<float4*>(g_h + (size_t)(b * NS + s) * HH);
        float4* dc = reinterpret_cast<float4*>(g_c + (size_t)(b * NS + s) * HH);
#pragma unroll
        for (int r = 0; r < 4; r++) {
            dh[lane + 32 * r] = sh[lane + 32 * r];
            dc[lane + 32 * r] = sc[lane + 32 * r];
        }
    }
    if (lane == 0) {
        // job A: new pair (seq[k-1], s), keyed by seq[k-1]
        g_jobs[b * 2]     = make_int4(skm1, skm1, s, (k >= 1) ? 1 : 0);
        // job B: new pair (s, seq[k+2]), keyed by s
        g_jobs[b * 2 + 1] = make_int4(s, s, skp2, (k <= npairs - 2) ? 1 : 0);
    }
    // sequence update: j<k keep, j==k -> s, j>k shift left
    int nxt = __shfl_down_sync(0xffffffffu, seqv, 1);
    int newv = (lane < k) ? seqv : ((lane == k) ? s : nxt);
    g_seq[b * 32 + lane] = newv;
}

// ---------------- output: h of the root slot ----------------
__global__ void out_k(float* __restrict__ out)
{
    int b = blockIdx.x;
    int s = g_seq[b * 32];
    const float4* src = reinterpret_cast<const float4*>(g_h + (size_t)(b * NS + s) * HH);
    reinterpret_cast<float4*>(out)[b * 128 + threadIdx.x] = src[threadIdx.x];
}

// ---------------- launch ----------------
extern "C" void kernel_launch(void* const* d_in, const int* in_sizes, int n_in,
                              void* d_out, int out_size)
{
    const float* x      = (const float*)d_in[0];
    const int*   length = (const int*)  d_in[1];
    const float* W_word = (const float*)d_in[2];
    const float* b_word = (const float*)d_in[3];
    const float* W_comp = (const float*)d_in[4];
    const float* b_comp = (const float*)d_in[5];
    const float* cq     = (const float*)d_in[6];
    float* out = (float*)d_out;

    init_k<<<32, 256>>>();
    // word projection: (B*L) x 1024, K=512
    gemm_k<<<dim3(128, 8), 256>>>(0, 0, x, W_word, b_word, W_comp);
    // leaf transforms: (B*L) x 5120, K=512
    gemm_k<<<dim3(128, 40), 256>>>(1, 0, x, W_word, b_word, W_comp);
    // initial candidates: 31 pairs per batch
    pair_k<<<BB * 31, 128>>>(b_comp, cq, 1);

    for (int i = 0; i < 31; i++) {
        plan_k<<<BB, 32>>>(length, i);
        if (i < 30) {
            // new-node transforms: 256 x 5120, K=512
            gemm_k<<<dim3(4, 40), 256>>>(2, i, x, W_word, b_word, W_comp);
            // recompute affected candidate pairs (<= 2 per batch)
            pair_k<<<BB * 2, 128>>>(b_comp, cq, 0);
        }
    }
    out_k<<<BB, 128>>>(out);
}

// round 2
// speedup vs baseline: 1.0018x; 1.0018x over previous
#include <cuda_runtime.h>
#include <math.h>

// Problem constants
#define BB   256   // batch
#define LL   32    // seq len
#define HH   512   // hidden
#define DD   512   // input dim
#define NS   64    // slot pool per batch (32 leaves + up to 31 composed)
#define G5   2560  // 5*H
// combined [Wl;Wr] output width = 2*G5 = 5120

// ---------------- static device scratch (no allocations allowed) ----------------
__device__ float g_h [BB * NS * HH];            // slot h vectors
__device__ float g_c [BB * NS * HH];            // slot c vectors
__device__ float g_ch[BB * NS * HH];            // candidate h, keyed by left slot id
__device__ float g_cc[BB * NS * HH];            // candidate c
__device__ float g_vl[(size_t)BB * NS * G5];    // Wl @ h_slot
__device__ float g_vr[(size_t)BB * NS * G5];    // Wr @ h_slot
__device__ float g_clog[BB * NS];               // candidate logits, keyed by left slot id
__device__ int   g_seq [BB * 32];               // current sequence: slot ids
__device__ int4  g_jobs[BB * 2];                // per-step recompute jobs {key, L, R, valid}

// ---------------- init: seq[b][j] = j ----------------
__global__ void init_k()
{
    int idx = blockIdx.x * blockDim.x + threadIdx.x;
    if (idx < BB * 32) g_seq[idx] = idx & 31;
}

// ---------------- generic SGEMM: C[M,N] = A[M,K=512] * W[N,K=512]^T ----------------
// mode 0: word projection  A=x rows,        W=W_word (1024 rows), out -> g_h/g_c leaves (+b_word)
// mode 1: leaf transforms  A=leaf h rows,   W=[Wl;Wr] (5120),     out -> g_vl/g_vr leaves
// mode 2: step transform   A=new-slot rows, W=[Wl;Wr] (5120),     out -> g_vl/g_vr slot 32+step
// Tile: BM=64, BN=128, BK=16, 256 threads, 4x8 microtile.
__global__ __launch_bounds__(256) void gemm_k(
    int mode, int step,
    const float* __restrict__ x, const float* __restrict__ W_word,
    const float* __restrict__ b_word, const float* __restrict__ W_comp)
{
    __shared__ __align__(16) float As[16][68];
    __shared__ __align__(16) float Bs[16][132];

    int tid = threadIdx.x;
    int ty = tid >> 4, tx = tid & 15;
    int m0 = blockIdx.x * 64;
    int n0 = blockIdx.y * 128;

    // A-tile load assignment: 1 float4 per thread
    int mI  = tid >> 2;         // 0..63
    int kqA = (tid & 3) * 4;    // 0,4,8,12
    {
    }
    const float* aptr;
    {
        int m = m0 + mI;
        if (mode == 0)      aptr = x + (size_t)m * DD;
        else if (mode == 1) aptr = g_h + (size_t)((m >> 5) * NS + (m & 31)) * HH;
        else                aptr = g_h + (size_t)(m * NS + 32 + step) * HH;
        aptr += kqA;
    }

    // B-tile load assignment: 2 float4 per thread
    const float* bptr[2];
    int kqB[2], nI[2];
#pragma unroll
    for (int r = 0; r < 2; r++) {
        int q = tid + r * 256;
        nI[r]  = q >> 2;            // 0..127
        kqB[r] = (q & 3) * 4;
        int n = n0 + nI[r];
        const float* wp;
        if (mode == 0) wp = W_word + (size_t)n * DD;
        else wp = (n < G5) ? (W_comp + (size_t)n * 1024)
                           : (W_comp + (size_t)(n - G5) * 1024 + 512);
        bptr[r] = wp + kqB[r];
    }

    float acc[4][8];
#pragma unroll
    for (int i = 0; i < 4; i++)
#pragma unroll
        for (int j = 0; j < 8; j++) acc[i][j] = 0.f;

    for (int k0 = 0; k0 < 512; k0 += 16) {
        float4 av = *reinterpret_cast<const float4*>(aptr + k0);
        As[kqA + 0][mI] = av.x;
        As[kqA + 1][mI] = av.y;
        As[kqA + 2][mI] = av.z;
        As[kqA + 3][mI] = av.w;
#pragma unroll
        for (int r = 0; r < 2; r++) {
            float4 bv = *reinterpret_cast<const float4*>(bptr[r] + k0);
            Bs[kqB[r] + 0][nI[r]] = bv.x;
            Bs[kqB[r] + 1][nI[r]] = bv.y;
            Bs[kqB[r] + 2][nI[r]] = bv.z;
            Bs[kqB[r] + 3][nI[r]] = bv.w;
        }
        __syncthreads();
#pragma unroll
        for (int kk = 0; kk < 16; kk++) {
            float a[4], b[8];
            *reinterpret_cast<float4*>(a)     = *reinterpret_cast<const float4*>(&As[kk][ty * 4]);
            *reinterpret_cast<float4*>(b)     = *reinterpret_cast<const float4*>(&Bs[kk][tx * 8]);
            *reinterpret_cast<float4*>(b + 4) = *reinterpret_cast<const float4*>(&Bs[kk][tx * 8 + 4]);
#pragma unroll
            for (int i = 0; i < 4; i++)
#pragma unroll
                for (int j = 0; j < 8; j++)
                    acc[i][j] = fmaf(a[i], b[j], acc[i][j]);
        }
        __syncthreads();
    }

    // epilogue
#pragma unroll
    for (int i = 0; i < 4; i++) {
        int m = m0 + ty * 4 + i;
#pragma unroll
        for (int j = 0; j < 8; j++) {
            int n = n0 + tx * 8 + j;
            float v = acc[i][j];
            if (mode == 0) {
                v += b_word[n];
                int bb = m >> 5, l = m & 31;
                if (n < HH) g_h[(size_t)(bb * NS + l) * HH + n] = v;
                else        g_c[(size_t)(bb * NS + l) * HH + (n - HH)] = v;
            } else {
                int bb, slot;
                if (mode == 1) { bb = m >> 5; slot = m & 31; }
                else           { bb = m;      slot = 32 + step; }
                size_t base = (size_t)(bb * NS + slot) * G5;
                if (n < G5) g_vl[base + n] = v;
                else        g_vr[base + (n - G5)] = v;
            }
        }
    }
}

// ---------------- pair gates + logit ----------------
__device__ __forceinline__ float sigf(float x) { return 1.f / (1.f + expf(-x)); }

__global__ __launch_bounds__(128) void pair_k(
    const float* __restrict__ b_comp, const float* __restrict__ cq, int initMode)
{
    int blk = blockIdx.x;
    int b, key, Ls, Rs;
    if (initMode) {
        b = blk / 31;
        int j = blk - b * 31;
        key = j; Ls = j; Rs = j + 1;
    } else {
        b = blk >> 1;
        int4 job = g_jobs[blk];
        if (!job.w) return;
        key = job.x; Ls = job.y; Rs = job.z;
    }
    int t = threadIdx.x;  // float4 index over H: 0..127

    const float4* vl = reinterpret_cast<const float4*>(g_vl + (size_t)(b * NS + Ls) * G5);
    const float4* vr = reinterpret_cast<const float4*>(g_vr + (size_t)(b * NS + Rs) * G5);
    const float4* bc = reinterpret_cast<const float4*>(b_comp);
    const float4* cl4 = reinterpret_cast<const float4*>(g_c + (size_t)(b * NS + Ls) * HH);
    const float4* cr4 = reinterpret_cast<const float4*>(g_c + (size_t)(b * NS + Rs) * HH);
    const float4* q4  = reinterpret_cast<const float4*>(cq);

    float vi[4], vfl[4], vfr[4], vu[4], vo[4];
    {
        float* dsts[5] = {vi, vfl, vfr, vu, vo};
#pragma unroll
        for (int g = 0; g < 5; g++) {
            float4 a  = vl[g * 128 + t];
            float4 bb = vr[g * 128 + t];
            float4 c  = bc[g * 128 + t];
            dsts[g][0] = a.x + bb.x + c.x;
            dsts[g][1] = a.y + bb.y + c.y;
            dsts[g][2] = a.z + bb.z + c.z;
            dsts[g][3] = a.w + bb.w + c.w;
        }
    }
    float4 cl = cl4[t], cr = cr4[t], qv = q4[t];
    float clv[4] = {cl.x, cl.y, cl.z, cl.w};
    float crv[4] = {cr.x, cr.y, cr.z, cr.w};
    float qa[4]  = {qv.x, qv.y, qv.z, qv.w};

    float hh[4], cc[4];
    float part = 0.f;
#pragma unroll
    for (int e = 0; e < 4; e++) {
        float c = clv[e] * sigf(vfl[e] + 1.f)
                + crv[e] * sigf(vfr[e] + 1.f)
                + tanhf(vu[e]) * sigf(vi[e]);
        float h = sigf(vo[e]) * tanhf(c);
        cc[e] = c; hh[e] = h;
        part = fmaf(qa[e], h, part);
    }
    reinterpret_cast<float4*>(g_ch + (size_t)(b * NS + key) * HH)[t] = make_float4(hh[0], hh[1], hh[2], hh[3]);
    reinterpret_cast<float4*>(g_cc + (size_t)(b * NS + key) * HH)[t] = make_float4(cc[0], cc[1], cc[2], cc[3]);

#pragma unroll
    for (int o = 16; o; o >>= 1) part += __shfl_xor_sync(0xffffffffu, part, o);
    __shared__ float ws[4];
    if ((t & 31) == 0) ws[t >> 5] = part;
    __syncthreads();
    if (t == 0) {
        float tot = ws[0] + ws[1] + ws[2] + ws[3];
        g_clog[b * NS + key] = tot * 0.044194173824159216f;  // 1/sqrt(512)
    }
}

// ---------------- per-step planner: mask, argmax, merge, emit jobs ----------------
__global__ void plan_k(const int* __restrict__ length, int i)
{
    int b = blockIdx.x;
    int lane = threadIdx.x;  // 32 lanes
    int ell = length[b];
    bool done = (i + 1 < ell);
    if (!done) {
        // sequence truncates implicitly (cur = 32 - i tracked by step index)
        if (lane == 0) {
            g_jobs[b * 2]     = make_int4(0, 0, 0, 0);
            g_jobs[b * 2 + 1] = make_int4(0, 0, 0, 0);
        }
        return;
    }
    int npairs = 31 - i;
    int seqv = g_seq[b * 32 + lane];
    bool valid = (lane < ell - i - 1);  // reference mask: (i+1+j) < length
    float lg = valid ? g_clog[b * NS + seqv] : -1e9f;

    float mx = lg;
#pragma unroll
    for (int o = 16; o; o >>= 1) mx = fmaxf(mx, __shfl_xor_sync(0xffffffffu, mx, o));
    unsigned bal = __ballot_sync(0xffffffffu, lg == mx);
    int k = __ffs(bal) - 1;  // first-max, matches jnp.argmax

    int s = 32 + i;  // new slot id
    int sk   = __shfl_sync(0xffffffffu, seqv, k);
    int skm1 = __shfl_sync(0xffffffffu, seqv, (k > 0) ? (k - 1) : 0);
    int skp2 = __shfl_sync(0xffffffffu, seqv, (k + 2 < 32) ? (k + 2) : 31);

    // selected candidate becomes the new node
    {
        const float4* sh = reinterpret_cast<const float4*>(g_ch + (size_t)(b * NS + sk) * HH);
        const float4* sc = reinterpret_cast<const float4*>(g_cc + (size_t)(b * NS + sk) * HH);
        float4* dh = reinterpret_cast<float4*>(g_h + (size_t)(b * NS + s) * HH);
        float4* dc = reinterpret_cast<float4*>(g_c + (size_t)(b * NS + s) * HH);
#pragma unroll
        for (int r = 0; r < 4; r++) {
            dh[lane + 32 * r] = sh[lane + 32 * r];
            dc[lane + 32 * r] = sc[lane + 32 * r];
        }
    }
    if (lane == 0) {
        // job A: new pair (seq[k-1], s), keyed by seq[k-1]
        g_jobs[b * 2]     = make_int4(skm1, skm1, s, (k >= 1) ? 1 : 0);
        // job B: new pair (s, seq[k+2]), keyed by s
        g_jobs[b * 2 + 1] = make_int4(s, s, skp2, (k <= npairs - 2) ? 1 : 0);
    }
    // sequence update: j<k keep, j==k -> s, j>k shift left
    int nxt = __shfl_down_sync(0xffffffffu, seqv, 1);
    int newv = (lane < k) ? seqv : ((lane == k) ? s : nxt);
    g_seq[b * 32 + lane] = newv;
}

// ---------------- output: h of the root slot ----------------
__global__ void out_k(float* __restrict__ out)
{
    int b = blockIdx.x;
    int s = g_seq[b * 32];
    const float4* src = reinterpret_cast<const float4*>(g_h + (size_t)(b * NS + s) * HH);
    reinterpret_cast<float4*>(out)[b * 128 + threadIdx.x] = src[threadIdx.x];
}

// ---------------- launch ----------------
extern "C" void kernel_launch(void* const* d_in, const int* in_sizes, int n_in,
                              void* d_out, int out_size)
{
    const float* x      = (const float*)d_in[0];
    const int*   length = (const int*)  d_in[1];
    const float* W_word = (const float*)d_in[2];
    const float* b_word = (const float*)d_in[3];
    const float* W_comp = (const float*)d_in[4];
    const float* b_comp = (const float*)d_in[5];
    const float* cq     = (const float*)d_in[6];
    float* out = (float*)d_out;

    init_k<<<32, 256>>>();
    // word projection: (B*L) x 1024, K=512
    gemm_k<<<dim3(128, 8), 256>>>(0, 0, x, W_word, b_word, W_comp);
    // leaf transforms: (B*L) x 5120, K=512
    gemm_k<<<dim3(128, 40), 256>>>(1, 0, x, W_word, b_word, W_comp);
    // initial candidates: 31 pairs per batch
    pair_k<<<BB * 31, 128>>>(b_comp, cq, 1);

    for (int i = 0; i < 31; i++) {
        plan_k<<<BB, 32>>>(length, i);
        if (i < 30) {
            // new-node transforms: 256 x 5120, K=512
            gemm_k<<<dim3(4, 40), 256>>>(2, i, x, W_word, b_word, W_comp);
            // recompute affected candidate pairs (<= 2 per batch)
            pair_k<<<BB * 2, 128>>>(b_comp, cq, 0);
        }
    }
    out_k<<<BB, 128>>>(out);
}

// round 3
// speedup vs baseline: 1.0160x; 1.0142x over previous
#include <cuda_runtime.h>
#include <math.h>

// Problem constants
#define BB   256   // batch
#define LL   32    // seq len
#define HH   512   // hidden
#define DD   512   // input dim
#define NS   64    // slot pool per batch (32 leaves + up to 31 composed)
#define G5   2560  // 5*H

// ---------------- static device scratch ----------------
__device__ float g_h [BB * NS * HH];            // slot h vectors
__device__ float g_c [BB * NS * HH];            // slot c vectors
__device__ float g_ch[BB * NS * HH];            // candidate h, keyed by left slot id
__device__ float g_cc[BB * NS * HH];            // candidate c
__device__ float g_vl[(size_t)BB * NS * G5];    // Wl @ h_slot
__device__ float g_vr[(size_t)BB * NS * G5];    // Wr @ h_slot
__device__ float g_clog[BB * NS];               // candidate logits, keyed by left slot id
__device__ int   g_seq [BB * 32];               // current sequence: slot ids
__device__ int4  g_jobs[BB * 2];                // per-step recompute jobs {key, L, R, valid}
__device__ int   g_active[BB];                  // compacted active batch list (per step)
__device__ int   g_nact[32];                    // active count per step

// ---------------- init ----------------
__global__ void init_k()
{
    int idx = blockIdx.x * blockDim.x + threadIdx.x;
    if (idx < BB * 32) g_seq[idx] = idx & 31;
    if (idx < 32) g_nact[idx] = 0;
}

// ---------------- big SGEMM: 128x128x8 double-buffered ----------------
// mode 0: word projection  A = x rows (M=8192), W = W_word (N=1024), +b_word -> g_h/g_c
// mode 1: leaf transforms  A = leaf h rows (M=8192), W = [Wl;Wr] (N=5120) -> g_vl/g_vr
__global__ __launch_bounds__(256, 2) void gemm_big_k(
    int mode,
    const float* __restrict__ x, const float* __restrict__ W_word,
    const float* __restrict__ b_word, const float* __restrict__ W_comp)
{
    __shared__ __align__(16) float As[2][8][132];
    __shared__ __align__(16) float Bs[2][8][132];

    const int tid = threadIdx.x;
    const int m0 = blockIdx.x * 128;
    const int n0 = blockIdx.y * 128;
    const int lrow = tid >> 1;        // 0..127
    const int kq   = (tid & 1) * 4;   // 0 or 4

    const float* aptr;
    {
        int m = m0 + lrow;
        if (mode == 0) aptr = x + (size_t)m * DD + kq;
        else           aptr = g_h + (size_t)((m >> 5) * NS + (m & 31)) * HH + kq;
    }
    const float* bptr;
    {
        int n = n0 + lrow;
        if (mode == 0) bptr = W_word + (size_t)n * DD + kq;
        else bptr = (n < G5) ? W_comp + (size_t)n * 1024 + kq
                             : W_comp + (size_t)(n - G5) * 1024 + 512 + kq;
    }

    const int ty = tid >> 4;   // 0..15 -> rows ty*8
    const int tx = tid & 15;   // 0..15 -> cols tx*8

    float acc[8][8];
#pragma unroll
    for (int i = 0; i < 8; i++)
#pragma unroll
        for (int j = 0; j < 8; j++) acc[i][j] = 0.f;

    float4 ra = *reinterpret_cast<const float4*>(aptr);
    float4 rb = *reinterpret_cast<const float4*>(bptr);
    As[0][kq + 0][lrow] = ra.x; As[0][kq + 1][lrow] = ra.y;
    As[0][kq + 2][lrow] = ra.z; As[0][kq + 3][lrow] = ra.w;
    Bs[0][kq + 0][lrow] = rb.x; Bs[0][kq + 1][lrow] = rb.y;
    Bs[0][kq + 2][lrow] = rb.z; Bs[0][kq + 3][lrow] = rb.w;
    __syncthreads();

    int buf = 0;
    for (int k0 = 8; k0 <= 512; k0 += 8) {
        const bool more = (k0 < 512);
        if (more) {
            ra = *reinterpret_cast<const float4*>(aptr + k0);
            rb = *reinterpret_cast<const float4*>(bptr + k0);
        }
#pragma unroll
        for (int kk = 0; kk < 8; kk++) {
            float a[8], b[8];
            *reinterpret_cast<float4*>(a)     = *reinterpret_cast<const float4*>(&As[buf][kk][ty * 8]);
            *reinterpret_cast<float4*>(a + 4) = *reinterpret_cast<const float4*>(&As[buf][kk][ty * 8 + 4]);
            *reinterpret_cast<float4*>(b)     = *reinterpret_cast<const float4*>(&Bs[buf][kk][tx * 8]);
            *reinterpret_cast<float4*>(b + 4) = *reinterpret_cast<const float4*>(&Bs[buf][kk][tx * 8 + 4]);
#pragma unroll
            for (int i = 0; i < 8; i++)
#pragma unroll
                for (int j = 0; j < 8; j++)
                    acc[i][j] = fmaf(a[i], b[j], acc[i][j]);
        }
        if (more) {
            As[buf ^ 1][kq + 0][lrow] = ra.x; As[buf ^ 1][kq + 1][lrow] = ra.y;
            As[buf ^ 1][kq + 2][lrow] = ra.z; As[buf ^ 1][kq + 3][lrow] = ra.w;
            Bs[buf ^ 1][kq + 0][lrow] = rb.x; Bs[buf ^ 1][kq + 1][lrow] = rb.y;
            Bs[buf ^ 1][kq + 2][lrow] = rb.z; Bs[buf ^ 1][kq + 3][lrow] = rb.w;
        }
        __syncthreads();
        buf ^= 1;
    }

    // epilogue
    const int nb = n0 + tx * 8;
    if (mode == 0) {
        float4 bi0 = *reinterpret_cast<const float4*>(&b_word[nb]);
        float4 bi1 = *reinterpret_cast<const float4*>(&b_word[nb + 4]);
#pragma unroll
        for (int i = 0; i < 8; i++) {
            int m = m0 + ty * 8 + i;
            int bb = m >> 5, l = m & 31;
            float* dst = (nb < HH) ? (g_h + (size_t)(bb * NS + l) * HH + nb)
                                   : (g_c + (size_t)(bb * NS + l) * HH + (nb - HH));
            float4 v0 = make_float4(acc[i][0] + bi0.x, acc[i][1] + bi0.y,
                                    acc[i][2] + bi0.z, acc[i][3] + bi0.w);
            float4 v1 = make_float4(acc[i][4] + bi1.x, acc[i][5] + bi1.y,
                                    acc[i][6] + bi1.z, acc[i][7] + bi1.w);
            *reinterpret_cast<float4*>(dst)     = v0;
            *reinterpret_cast<float4*>(dst + 4) = v1;
        }
    } else {
#pragma unroll
        for (int i = 0; i < 8; i++) {
            int m = m0 + ty * 8 + i;
            int bb = m >> 5, l = m & 31;
            size_t base = (size_t)(bb * NS + l) * G5;
            float* dst = (nb < G5) ? (g_vl + base + nb) : (g_vr + base + (nb - G5));
            *reinterpret_cast<float4*>(dst)     = make_float4(acc[i][0], acc[i][1], acc[i][2], acc[i][3]);
            *reinterpret_cast<float4*>(dst + 4) = make_float4(acc[i][4], acc[i][5], acc[i][6], acc[i][7]);
        }
    }
}

// ---------------- step SGEMM: 32x128x8, compacted active batches ----------------
// A = h of new node (slot 32+step) for active batches; N = 5120 -> g_vl/g_vr
__global__ __launch_bounds__(256) void gemm_step_k(
    int step, const float* __restrict__ W_comp)
{
    const int nact = g_nact[step];
    const int m0 = blockIdx.x * 32;
    if (m0 >= nact) return;

    __shared__ __align__(16) float As[2][8][36];
    __shared__ __align__(16) float Bs[2][8][132];

    const int tid = threadIdx.x;
    const int n0 = blockIdx.y * 128;

    // B loader: all 256 threads
    const int brow = tid >> 1;
    const int kqB  = (tid & 1) * 4;
    const float* bptr;
    {
        int n = n0 + brow;
        bptr = (n < G5) ? W_comp + (size_t)n * 1024 + kqB
                        : W_comp + (size_t)(n - G5) * 1024 + 512 + kqB;
    }
    // A loader: first 64 threads
    const bool aact = (tid < 64);
    const int arow = tid >> 1;
    const int kqA  = (tid & 1) * 4;
    const float* aptr = g_h + kqA;  // safe dummy
    if (aact) {
        int m = m0 + arow;
        if (m < nact) {
            int b = g_active[m];
            aptr = g_h + (size_t)(b * NS + 32 + step) * HH + kqA;
        }
    }

    const int ty = tid >> 4;   // rows ty*2
    const int tx = tid & 15;   // cols tx*8

    float acc[2][8];
#pragma unroll
    for (int i = 0; i < 2; i++)
#pragma unroll
        for (int j = 0; j < 8; j++) acc[i][j] = 0.f;

    float4 ra, rb;
    rb = *reinterpret_cast<const float4*>(bptr);
    if (aact) {
        ra = *reinterpret_cast<const float4*>(aptr);
        As[0][kqA + 0][arow] = ra.x; As[0][kqA + 1][arow] = ra.y;
        As[0][kqA + 2][arow] = ra.z; As[0][kqA + 3][arow] = ra.w;
    }
    Bs[0][kqB + 0][brow] = rb.x; Bs[0][kqB + 1][brow] = rb.y;
    Bs[0][kqB + 2][brow] = rb.z; Bs[0][kqB + 3][brow] = rb.w;
    __syncthreads();

    int buf = 0;
    for (int k0 = 8; k0 <= 512; k0 += 8) {
        const bool more = (k0 < 512);
        if (more) {
            if (aact) ra = *reinterpret_cast<const float4*>(aptr + k0);
            rb = *reinterpret_cast<const float4*>(bptr + k0);
        }
#pragma unroll
        for (int kk = 0; kk < 8; kk++) {
            float a[2], b[8];
            *reinterpret_cast<float2*>(a)     = *reinterpret_cast<const float2*>(&As[buf][kk][ty * 2]);
            *reinterpret_cast<float4*>(b)     = *reinterpret_cast<const float4*>(&Bs[buf][kk][tx * 8]);
            *reinterpret_cast<float4*>(b + 4) = *reinterpret_cast<const float4*>(&Bs[buf][kk][tx * 8 + 4]);
#pragma unroll
            for (int i = 0; i < 2; i++)
#pragma unroll
                for (int j = 0; j < 8; j++)
                    acc[i][j] = fmaf(a[i], b[j], acc[i][j]);
        }
        if (more) {
            if (aact) {
                As[buf ^ 1][kqA + 0][arow] = ra.x; As[buf ^ 1][kqA + 1][arow] = ra.y;
                As[buf ^ 1][kqA + 2][arow] = ra.z; As[buf ^ 1][kqA + 3][arow] = ra.w;
            }
            Bs[buf ^ 1][kqB + 0][brow] = rb.x; Bs[buf ^ 1][kqB + 1][brow] = rb.y;
            Bs[buf ^ 1][kqB + 2][brow] = rb.z; Bs[buf ^ 1][kqB + 3][brow] = rb.w;
        }
        __syncthreads();
        buf ^= 1;
    }

    const int nb = n0 + tx * 8;
#pragma unroll
    for (int i = 0; i < 2; i++) {
        int m = m0 + ty * 2 + i;
        if (m < nact) {
            int b = g_active[m];
            size_t base = (size_t)(b * NS + 32 + step) * G5;
            float* dst = (nb < G5) ? (g_vl + base + nb) : (g_vr + base + (nb - G5));
            *reinterpret_cast<float4*>(dst)     = make_float4(acc[i][0], acc[i][1], acc[i][2], acc[i][3]);
            *reinterpret_cast<float4*>(dst + 4) = make_float4(acc[i][4], acc[i][5], acc[i][6], acc[i][7]);
        }
    }
}

// ---------------- pair gates + logit ----------------
__device__ __forceinline__ float sigf(float x) { return 1.f / (1.f + expf(-x)); }

__global__ __launch_bounds__(128) void pair_k(
    const float* __restrict__ b_comp, const float* __restrict__ cq, int initMode)
{
    int blk = blockIdx.x;
    int b, key, Ls, Rs;
    if (initMode) {
        b = blk / 31;
        int j = blk - b * 31;
        key = j; Ls = j; Rs = j + 1;
    } else {
        b = blk >> 1;
        int4 job = g_jobs[blk];
        if (!job.w) return;
        key = job.x; Ls = job.y; Rs = job.z;
    }
    int t = threadIdx.x;  // float4 index over H: 0..127

    const float4* vl = reinterpret_cast<const float4*>(g_vl + (size_t)(b * NS + Ls) * G5);
    const float4* vr = reinterpret_cast<const float4*>(g_vr + (size_t)(b * NS + Rs) * G5);
    const float4* bc = reinterpret_cast<const float4*>(b_comp);
    const float4* cl4 = reinterpret_cast<const float4*>(g_c + (size_t)(b * NS + Ls) * HH);
    const float4* cr4 = reinterpret_cast<const float4*>(g_c + (size_t)(b * NS + Rs) * HH);
    const float4* q4  = reinterpret_cast<const float4*>(cq);

    float vi[4], vfl[4], vfr[4], vu[4], vo[4];
    {
        float* dsts[5] = {vi, vfl, vfr, vu, vo};
#pragma unroll
        for (int g = 0; g < 5; g++) {
            float4 a  = vl[g * 128 + t];
            float4 bb = vr[g * 128 + t];
            float4 c  = bc[g * 128 + t];
            dsts[g][0] = a.x + bb.x + c.x;
            dsts[g][1] = a.y + bb.y + c.y;
            dsts[g][2] = a.z + bb.z + c.z;
            dsts[g][3] = a.w + bb.w + c.w;
        }
    }
    float4 cl = cl4[t], cr = cr4[t], qv = q4[t];
    float clv[4] = {cl.x, cl.y, cl.z, cl.w};
    float crv[4] = {cr.x, cr.y, cr.z, cr.w};
    float qa[4]  = {qv.x, qv.y, qv.z, qv.w};

    float hh[4], cc[4];
    float part = 0.f;
#pragma unroll
    for (int e = 0; e < 4; e++) {
        float c = clv[e] * sigf(vfl[e] + 1.f)
                + crv[e] * sigf(vfr[e] + 1.f)
                + tanhf(vu[e]) * sigf(vi[e]);
        float h = sigf(vo[e]) * tanhf(c);
        cc[e] = c; hh[e] = h;
        part = fmaf(qa[e], h, part);
    }
    reinterpret_cast<float4*>(g_ch + (size_t)(b * NS + key) * HH)[t] = make_float4(hh[0], hh[1], hh[2], hh[3]);
    reinterpret_cast<float4*>(g_cc + (size_t)(b * NS + key) * HH)[t] = make_float4(cc[0], cc[1], cc[2], cc[3]);

#pragma unroll
    for (int o = 16; o; o >>= 1) part += __shfl_xor_sync(0xffffffffu, part, o);
    __shared__ float ws[4];
    if ((t & 31) == 0) ws[t >> 5] = part;
    __syncthreads();
    if (t == 0) {
        float tot = ws[0] + ws[1] + ws[2] + ws[3];
        g_clog[b * NS + key] = tot * 0.044194173824159216f;  // 1/sqrt(512)
    }
}

// ---------------- per-step planner: mask, argmax, merge, compaction, jobs ----------------
__global__ void plan_k(const int* __restrict__ length, int i)
{
    int b = blockIdx.x;
    int lane = threadIdx.x;  // 32 lanes
    int ell = length[b];
    bool act = (i + 1 < ell);
    if (!act) {
        if (lane == 0) {
            g_jobs[b * 2]     = make_int4(0, 0, 0, 0);
            g_jobs[b * 2 + 1] = make_int4(0, 0, 0, 0);
        }
        return;
    }
    int npairs = 31 - i;
    int seqv = g_seq[b * 32 + lane];
    bool valid = (lane < ell - i - 1);  // reference mask: (i+1+j) < length
    float lg = valid ? g_clog[b * NS + seqv] : -1e9f;

    float mx = lg;
#pragma unroll
    for (int o = 16; o; o >>= 1) mx = fmaxf(mx, __shfl_xor_sync(0xffffffffu, mx, o));
    unsigned bal = __ballot_sync(0xffffffffu, lg == mx);
    int k = __ffs(bal) - 1;  // first-max, matches jnp.argmax

    int s = 32 + i;  // new slot id
    int sk   = __shfl_sync(0xffffffffu, seqv, k);
    int skm1 = __shfl_sync(0xffffffffu, seqv, (k > 0) ? (k - 1) : 0);
    int skp2 = __shfl_sync(0xffffffffu, seqv, (k + 2 < 32) ? (k + 2) : 31);

    // selected candidate becomes the new node
    {
        const float4* sh = reinterpret_cast<const float4*>(g_ch + (size_t)(b * NS + sk) * HH);
        const float4* sc = reinterpret_cast<const float4*>(g_cc + (size_t)(b * NS + sk) * HH);
        float4* dh = reinterpret_cast<float4*>(g_h + (size_t)(b * NS + s) * HH);
        float4* dc = reinterpret_cast<float4*>(g_c + (size_t)(b * NS + s) * HH);
#pragma unroll
        for (int r = 0; r < 4; r++) {
            dh[lane + 32 * r] = sh[lane + 32 * r];
            dc[lane + 32 * r] = sc[lane + 32 * r];
        }
    }
    if (lane == 0) {
        // compaction for the step GEMM
        int idx = atomicAdd(&g_nact[i], 1);
        g_active[idx] = b;
        // job A: new pair (seq[k-1], s), keyed by seq[k-1]
        g_jobs[b * 2]     = make_int4(skm1, skm1, s, (k >= 1) ? 1 : 0);
        // job B: new pair (s, seq[k+2]), keyed by s
        g_jobs[b * 2 + 1] = make_int4(s, s, skp2, (k <= npairs - 2) ? 1 : 0);
    }
    // sequence update: j<k keep, j==k -> s, j>k shift left
    int nxt = __shfl_down_sync(0xffffffffu, seqv, 1);
    int newv = (lane < k) ? seqv : ((lane == k) ? s : nxt);
    g_seq[b * 32 + lane] = newv;
}

// ---------------- output: h of the root slot ----------------
__global__ void out_k(float* __restrict__ out)
{
    int b = blockIdx.x;
    int s = g_seq[b * 32];
    const float4* src = reinterpret_cast<const float4*>(g_h + (size_t)(b * NS + s) * HH);
    reinterpret_cast<float4*>(out)[b * 128 + threadIdx.x] = src[threadIdx.x];
}

// ---------------- launch ----------------
extern "C" void kernel_launch(void* const* d_in, const int* in_sizes, int n_in,
                              void* d_out, int out_size)
{
    const float* x      = (const float*)d_in[0];
    const int*   length = (const int*)  d_in[1];
    const float* W_word = (const float*)d_in[2];
    const float* b_word = (const float*)d_in[3];
    const float* W_comp = (const float*)d_in[4];
    const float* b_comp = (const float*)d_in[5];
    const float* cq     = (const float*)d_in[6];
    float* out = (float*)d_out;

    init_k<<<32, 256>>>();
    // word projection: (B*L) x 1024, K=512
    gemm_big_k<<<dim3(64, 8), 256>>>(0, x, W_word, b_word, W_comp);
    // leaf transforms: (B*L) x 5120, K=512
    gemm_big_k<<<dim3(64, 40), 256>>>(1, x, W_word, b_word, W_comp);
    // initial candidates: 31 pairs per batch
    pair_k<<<BB * 31, 128>>>(b_comp, cq, 1);

    for (int i = 0; i < 31; i++) {
        plan_k<<<BB, 32>>>(length, i);
        if (i < 30) {
            // new-node transforms: active x 5120, K=512 (early-exit blocks)
            gemm_step_k<<<dim3(8, 40), 256>>>(i, W_comp);
            // recompute affected candidate pairs (<= 2 per batch)
            pair_k<<<BB * 2, 128>>>(b_comp, cq, 0);
        }
    }
    out_k<<<BB, 128>>>(out);
}

// round 4
// speedup vs baseline: 1.5141x; 1.4903x over previous
#include <cuda_runtime.h>
#include <math.h>

// Problem constants
#define BB   256
#define LL   32
#define HH   512
#define DD   512
#define NS   64
#define G5   2560
#define GRID 148
#define TPB  256

// ---------------- static device scratch ----------------
__device__ float g_h [BB * NS * HH];
__device__ float g_c [BB * NS * HH];
__device__ float g_ch[BB * NS * HH];
__device__ float g_cc[BB * NS * HH];
__device__ float g_vl[(size_t)BB * NS * G5];
__device__ float g_vr[(size_t)BB * NS * G5];
__device__ float g_clog[BB * NS];
__device__ int   g_seq [BB * 32];
__device__ int4  g_jobs[BB * 2];
__device__ int   g_active[BB];
__device__ int   g_nact[32];
__device__ int   g_bar_cnt = 0;
__device__ volatile int g_bar_gen = 0;

__device__ __forceinline__ float sigf(float x) { return 1.f / (1.f + expf(-x)); }

// ---------------- software grid barrier (all 148 blocks co-resident) ----------------
__device__ __forceinline__ void gbar(int tid, int* gen)
{
    __syncthreads();
    if (tid == 0) {
        int target = *gen + 1;
        __threadfence();
        if (atomicAdd(&g_bar_cnt, 1) == GRID - 1) {
            g_bar_cnt = 0;
            __threadfence();
            g_bar_gen = target;
        } else {
            while (g_bar_gen - target < 0) __nanosleep(32);
            __threadfence();   // gpu-scope fence: CCTL.IVALL -> drop stale L1 lines
        }
        *gen = target;
    }
    __syncthreads();
}

// ---------------- big GEMM tile: 128x128xK512, BK=8 double-buffered ----------------
// mode 0: word projection  A = x rows, B = W_word rows, +b_word -> g_h/g_c leaves
// mode 1: leaf transforms  A = leaf h rows, B = [Wl;Wr] rows -> g_vl/g_vr leaves
#define ASI(b,k,r) As[((b)*8+(k))*132 + (r)]
#define BSI(b,k,r) Bs[((b)*8+(k))*132 + (r)]
__device__ void gemm_big_tile(int mode, int m0, int n0, int tid,
    float* __restrict__ As, float* __restrict__ Bs,
    const float* __restrict__ x, const float* __restrict__ W_word,
    const float* __restrict__ b_word, const float* __restrict__ W_comp)
{
    const int lrow = tid >> 1;
    const int kq   = (tid & 1) * 4;

    const float* aptr;
    {
        int m = m0 + lrow;
        aptr = (mode == 0) ? x + (size_t)m * DD + kq
                           : g_h + (size_t)((m >> 5) * NS + (m & 31)) * HH + kq;
    }
    const float* bptr;
    {
        int n = n0 + lrow;
        if (mode == 0) bptr = W_word + (size_t)n * DD + kq;
        else bptr = (n < G5) ? W_comp + (size_t)n * 1024 + kq
                             : W_comp + (size_t)(n - G5) * 1024 + 512 + kq;
    }

    const int ty = tid >> 4;
    const int tx = tid & 15;

    float acc[8][8];
#pragma unroll
    for (int i = 0; i < 8; i++)
#pragma unroll
        for (int j = 0; j < 8; j++) acc[i][j] = 0.f;

    float4 ra = *reinterpret_cast<const float4*>(aptr);
    float4 rb = *reinterpret_cast<const float4*>(bptr);
    ASI(0, kq + 0, lrow) = ra.x; ASI(0, kq + 1, lrow) = ra.y;
    ASI(0, kq + 2, lrow) = ra.z; ASI(0, kq + 3, lrow) = ra.w;
    BSI(0, kq + 0, lrow) = rb.x; BSI(0, kq + 1, lrow) = rb.y;
    BSI(0, kq + 2, lrow) = rb.z; BSI(0, kq + 3, lrow) = rb.w;
    __syncthreads();

    int buf = 0;
    for (int k0 = 8; k0 <= 512; k0 += 8) {
        const bool more = (k0 < 512);
        if (more) {
            ra = *reinterpret_cast<const float4*>(aptr + k0);
            rb = *reinterpret_cast<const float4*>(bptr + k0);
        }
#pragma unroll
        for (int kk = 0; kk < 8; kk++) {
            float a[8], b[8];
            *reinterpret_cast<float4*>(a)     = *reinterpret_cast<const float4*>(&ASI(buf, kk, ty * 8));
            *reinterpret_cast<float4*>(a + 4) = *reinterpret_cast<const float4*>(&ASI(buf, kk, ty * 8 + 4));
            *reinterpret_cast<float4*>(b)     = *reinterpret_cast<const float4*>(&BSI(buf, kk, tx * 8));
            *reinterpret_cast<float4*>(b + 4) = *reinterpret_cast<const float4*>(&BSI(buf, kk, tx * 8 + 4));
#pragma unroll
            for (int i = 0; i < 8; i++)
#pragma unroll
                for (int j = 0; j < 8; j++)
                    acc[i][j] = fmaf(a[i], b[j], acc[i][j]);
        }
        if (more) {
            ASI(buf ^ 1, kq + 0, lrow) = ra.x; ASI(buf ^ 1, kq + 1, lrow) = ra.y;
            ASI(buf ^ 1, kq + 2, lrow) = ra.z; ASI(buf ^ 1, kq + 3, lrow) = ra.w;
            BSI(buf ^ 1, kq + 0, lrow) = rb.x; BSI(buf ^ 1, kq + 1, lrow) = rb.y;
            BSI(buf ^ 1, kq + 2, lrow) = rb.z; BSI(buf ^ 1, kq + 3, lrow) = rb.w;
        }
        __syncthreads();
        buf ^= 1;
    }

    const int nb = n0 + tx * 8;
    if (mode == 0) {
        float4 bi0 = *reinterpret_cast<const float4*>(&b_word[nb]);
        float4 bi1 = *reinterpret_cast<const float4*>(&b_word[nb + 4]);
#pragma unroll
        for (int i = 0; i < 8; i++) {
            int m = m0 + ty * 8 + i;
            int bb = m >> 5, l = m & 31;
            float* dst = (nb < HH) ? (g_h + (size_t)(bb * NS + l) * HH + nb)
                                   : (g_c + (size_t)(bb * NS + l) * HH + (nb - HH));
            *reinterpret_cast<float4*>(dst)     = make_float4(acc[i][0] + bi0.x, acc[i][1] + bi0.y,
                                                              acc[i][2] + bi0.z, acc[i][3] + bi0.w);
            *reinterpret_cast<float4*>(dst + 4) = make_float4(acc[i][4] + bi1.x, acc[i][5] + bi1.y,
                                                              acc[i][6] + bi1.z, acc[i][7] + bi1.w);
        }
    } else {
#pragma unroll
        for (int i = 0; i < 8; i++) {
            int m = m0 + ty * 8 + i;
            int bb = m >> 5, l = m & 31;
            size_t base = (size_t)(bb * NS + l) * G5;
            float* dst = (nb < G5) ? (g_vl + base + nb) : (g_vr + base + (nb - G5));
            *reinterpret_cast<float4*>(dst)     = make_float4(acc[i][0], acc[i][1], acc[i][2], acc[i][3]);
            *reinterpret_cast<float4*>(dst + 4) = make_float4(acc[i][4], acc[i][5], acc[i][6], acc[i][7]);
        }
    }
}

// ---------------- step GEMM tile: 64x64xK512, BK=8 double-buffered ----------------
#define AS2(b,k,r) As[((b)*8+(k))*68 + (r)]
#define BS2(b,k,r) Bs[((b)*8+(k))*68 + (r)]
__device__ void gemm_step_tile(int step, int nact, int m0, int n0, int tid,
    float* __restrict__ As, float* __restrict__ Bs, const float* __restrict__ W_comp)
{
    const bool isA = (tid < 128);
    const int lt   = isA ? tid : tid - 128;
    const int lrow = lt >> 1;        // 0..63
    const int kq   = (lt & 1) * 4;   // 0 or 4

    const float* ptr;
    if (isA) {
        int m = m0 + lrow;
        if (m < nact) {
            int b = g_active[m];
            ptr = g_h + (size_t)(b * NS + 32 + step) * HH + kq;
        } else ptr = g_h + kq;   // valid dummy, masked in epilogue
    } else {
        int n = n0 + lrow;
        ptr = (n < G5) ? W_comp + (size_t)n * 1024 + kq
                       : W_comp + (size_t)(n - G5) * 1024 + 512 + kq;
    }

    const int ty = tid >> 4;
    const int tx = tid & 15;

    float acc[4][4];
#pragma unroll
    for (int i = 0; i < 4; i++)
#pragma unroll
        for (int j = 0; j < 4; j++) acc[i][j] = 0.f;

    float4 r = *reinterpret_cast<const float4*>(ptr);
    if (isA) {
        AS2(0, kq + 0, lrow) = r.x; AS2(0, kq + 1, lrow) = r.y;
        AS2(0, kq + 2, lrow) = r.z; AS2(0, kq + 3, lrow) = r.w;
    } else {
        BS2(0, kq + 0, lrow) = r.x; BS2(0, kq + 1, lrow) = r.y;
        BS2(0, kq + 2, lrow) = r.z; BS2(0, kq + 3, lrow) = r.w;
    }
    __syncthreads();

    int buf = 0;
    for (int k0 = 8; k0 <= 512; k0 += 8) {
        const bool more = (k0 < 512);
        if (more) r = *reinterpret_cast<const float4*>(ptr + k0);
#pragma unroll
        for (int kk = 0; kk < 8; kk++) {
            float a[4], b[4];
            *reinterpret_cast<float4*>(a) = *reinterpret_cast<const float4*>(&AS2(buf, kk, ty * 4));
            *reinterpret_cast<float4*>(b) = *reinterpret_cast<const float4*>(&BS2(buf, kk, tx * 4));
#pragma unroll
            for (int i = 0; i < 4; i++)
#pragma unroll
                for (int j = 0; j < 4; j++)
                    acc[i][j] = fmaf(a[i], b[j], acc[i][j]);
        }
        if (more) {
            if (isA) {
                AS2(buf ^ 1, kq + 0, lrow) = r.x; AS2(buf ^ 1, kq + 1, lrow) = r.y;
                AS2(buf ^ 1, kq + 2, lrow) = r.z; AS2(buf ^ 1, kq + 3, lrow) = r.w;
            } else {
                BS2(buf ^ 1, kq + 0, lrow) = r.x; BS2(buf ^ 1, kq + 1, lrow) = r.y;
                BS2(buf ^ 1, kq + 2, lrow) = r.z; BS2(buf ^ 1, kq + 3, lrow) = r.w;
            }
        }
        __syncthreads();
        buf ^= 1;
    }

    const int nb = n0 + tx * 4;
#pragma unroll
    for (int i = 0; i < 4; i++) {
        int m = m0 + ty * 4 + i;
        if (m < nact) {
            int b = g_active[m];
            size_t base = (size_t)(b * NS + 32 + step) * G5;
            float* dst = (nb < G5) ? (g_vl + base + nb) : (g_vr + base + (nb - G5));
            *reinterpret_cast<float4*>(dst) = make_float4(acc[i][0], acc[i][1], acc[i][2], acc[i][3]);
        }
    }
}

// ---------------- pair gates + partial logit (one 128-thread group, t in 0..127) ----
__device__ __forceinline__ float pair_body(int b, int key, int Ls, int Rs, int t,
    const float* __restrict__ b_comp, const float* __restrict__ cq)
{
    const float4* vl  = reinterpret_cast<const float4*>(g_vl + (size_t)(b * NS + Ls) * G5);
    const float4* vr  = reinterpret_cast<const float4*>(g_vr + (size_t)(b * NS + Rs) * G5);
    const float4* bc  = reinterpret_cast<const float4*>(b_comp);
    const float4* cl4 = reinterpret_cast<const float4*>(g_c + (size_t)(b * NS + Ls) * HH);
    const float4* cr4 = reinterpret_cast<const float4*>(g_c + (size_t)(b * NS + Rs) * HH);
    const float4* q4  = reinterpret_cast<const float4*>(cq);

    float vi[4], vfl[4], vfr[4], vu[4], vo[4];
    {
        float* dsts[5] = {vi, vfl, vfr, vu, vo};
#pragma unroll
        for (int g = 0; g < 5; g++) {
            float4 a  = vl[g * 128 + t];
            float4 bb = vr[g * 128 + t];
            float4 c  = bc[g * 128 + t];
            dsts[g][0] = a.x + bb.x + c.x;
            dsts[g][1] = a.y + bb.y + c.y;
            dsts[g][2] = a.z + bb.z + c.z;
            dsts[g][3] = a.w + bb.w + c.w;
        }
    }
    float4 cl = cl4[t], cr = cr4[t], qv = q4[t];
    float clv[4] = {cl.x, cl.y, cl.z, cl.w};
    float crv[4] = {cr.x, cr.y, cr.z, cr.w};
    float qa[4]  = {qv.x, qv.y, qv.z, qv.w};

    float hh[4], cc[4];
    float part = 0.f;
#pragma unroll
    for (int e = 0; e < 4; e++) {
        float c = clv[e] * sigf(vfl[e] + 1.f)
                + crv[e] * sigf(vfr[e] + 1.f)
                + tanhf(vu[e]) * sigf(vi[e]);
        float h = sigf(vo[e]) * tanhf(c);
        cc[e] = c; hh[e] = h;
        part = fmaf(qa[e], h, part);
    }
    reinterpret_cast<float4*>(g_ch + (size_t)(b * NS + key) * HH)[t] = make_float4(hh[0], hh[1], hh[2], hh[3]);
    reinterpret_cast<float4*>(g_cc + (size_t)(b * NS + key) * HH)[t] = make_float4(cc[0], cc[1], cc[2], cc[3]);
    return part;
}

// ---------------- the persistent kernel ----------------
__global__ __launch_bounds__(TPB, 1) void persist_k(
    const float* __restrict__ x, const int* __restrict__ length,
    const float* __restrict__ W_word, const float* __restrict__ b_word,
    const float* __restrict__ W_comp, const float* __restrict__ b_comp,
    const float* __restrict__ cq, float* __restrict__ out)
{
    __shared__ __align__(16) float As[2112];   // big: [2][8][132]; step: [2][8][68]
    __shared__ __align__(16) float Bs[2112];
    __shared__ float sws[8];

    const int tid = threadIdx.x;
    const int bid = blockIdx.x;
    int gen = 0;
    if (tid == 0) gen = g_bar_gen;

    // ---- init (block 0; consumed only after several barriers) ----
    if (bid == 0) {
        for (int idx = tid; idx < BB * 32; idx += TPB) g_seq[idx] = idx & 31;
        if (tid < 32) g_nact[tid] = 0;
    }

    // ---- phase A: word projection, 64 x 8 = 512 tiles ----
    for (int t = bid; t < 512; t += GRID)
        gemm_big_tile(0, (t & 63) * 128, (t >> 6) * 128, tid, As, Bs, x, W_word, b_word, W_comp);
    gbar(tid, &gen);

    // ---- phase B: leaf transforms, 64 x 40 = 2560 tiles ----
    for (int t = bid; t < 2560; t += GRID)
        gemm_big_tile(1, (t & 63) * 128, (t >> 6) * 128, tid, As, Bs, x, W_word, b_word, W_comp);
    gbar(tid, &gen);

    // ---- phase C: initial candidates, 256*31 jobs, 2 per block per iter ----
    {
        const int half = tid >> 7;
        const int t    = tid & 127;
        const int w    = t >> 5, lane = t & 31;
        for (int p = bid; p < 3968; p += GRID) {
            int j  = p * 2 + half;
            int b  = j / 31;
            int jj = j - b * 31;
            float part = pair_body(b, jj, jj, jj + 1, t, b_comp, cq);
#pragma unroll
            for (int o = 16; o; o >>= 1) part += __shfl_xor_sync(0xffffffffu, part, o);
            if (lane == 0) sws[half * 4 + w] = part;
            __syncthreads();
            if (t == 0) {
                float tot = sws[half * 4] + sws[half * 4 + 1] + sws[half * 4 + 2] + sws[half * 4 + 3];
                g_clog[b * NS + jj] = tot * 0.044194173824159216f;
            }
            __syncthreads();
        }
    }
    gbar(tid, &gen);

    // ---- main loop ----
    for (int i = 0; i < 31; i++) {
        // plan: blocks 0..127, warps 0..1, one batch per warp
        if (bid < 128 && (tid >> 5) < 2) {
            int b    = bid * 2 + (tid >> 5);
            int lane = tid & 31;
            int ell  = length[b];
            if (i + 1 < ell) {
                int npairs = 31 - i;
                int seqv = g_seq[b * 32 + lane];
                bool valid = (lane < ell - i - 1);
                float lg = valid ? g_clog[b * NS + seqv] : -1e9f;
                float mx = lg;
#pragma unroll
                for (int o = 16; o; o >>= 1) mx = fmaxf(mx, __shfl_xor_sync(0xffffffffu, mx, o));
                unsigned bal = __ballot_sync(0xffffffffu, lg == mx);
                int k = __ffs(bal) - 1;   // first-max, matches jnp.argmax

                int s    = 32 + i;
                int sk   = __shfl_sync(0xffffffffu, seqv, k);
                int skm1 = __shfl_sync(0xffffffffu, seqv, (k > 0) ? (k - 1) : 0);
                int skp2 = __shfl_sync(0xffffffffu, seqv, (k + 2 < 32) ? (k + 2) : 31);

                const float4* sh = reinterpret_cast<const float4*>(g_ch + (size_t)(b * NS + sk) * HH);
                const float4* sc = reinterpret_cast<const float4*>(g_cc + (size_t)(b * NS + sk) * HH);
                float4* dh = reinterpret_cast<float4*>(g_h + (size_t)(b * NS + s) * HH);
                float4* dc = reinterpret_cast<float4*>(g_c + (size_t)(b * NS + s) * HH);
#pragma unroll
                for (int r = 0; r < 4; r++) {
                    dh[lane + 32 * r] = sh[lane + 32 * r];
                    dc[lane + 32 * r] = sc[lane + 32 * r];
                }
                if (lane == 0) {
                    int idx = atomicAdd(&g_nact[i], 1);
                    g_active[idx] = b;
                    g_jobs[b * 2]     = make_int4(skm1, skm1, s, (k >= 1) ? 1 : 0);
                    g_jobs[b * 2 + 1] = make_int4(s, s, skp2, (k <= npairs - 2) ? 1 : 0);
                }
                int nxt = __shfl_down_sync(0xffffffffu, seqv, 1);
                int newv = (lane < k) ? seqv : ((lane == k) ? s : nxt);
                g_seq[b * 32 + lane] = newv;
            } else if ((tid & 31) == 0) {
                g_jobs[b * 2]     = make_int4(0, 0, 0, 0);
                g_jobs[b * 2 + 1] = make_int4(0, 0, 0, 0);
            }
        }
        gbar(tid, &gen);

        if (i < 30) {
            // step GEMM on compacted active batches
            int nact = g_nact[i];
            int ntile = ((nact + 63) >> 6) * 80;
            for (int t = bid; t < ntile; t += GRID)
                gemm_step_tile(i, nact, (t / 80) * 64, (t % 80) * 64, tid, As, Bs, W_comp);
            gbar(tid, &gen);

            // recompute affected candidate pairs (512 job slots)
            {
                const int half = tid >> 7;
                const int t    = tid & 127;
                const int w    = t >> 5, lane = t & 31;
                for (int p = bid; p < 256; p += GRID) {
                    int j = p * 2 + half;
                    int4 job = g_jobs[j];
                    int b = j >> 1;
                    bool act = (job.w != 0);
                    float part = act ? pair_body(b, job.x, job.y, job.z, t, b_comp, cq) : 0.f;
#pragma unroll
                    for (int o = 16; o; o >>= 1) part += __shfl_xor_sync(0xffffffffu, part, o);
                    if (lane == 0) sws[half * 4 + w] = part;
                    __syncthreads();
                    if (t == 0 && act) {
                        float tot = sws[half * 4] + sws[half * 4 + 1] + sws[half * 4 + 2] + sws[half * 4 + 3];
                        g_clog[b * NS + job.x] = tot * 0.044194173824159216f;
                    }
                    __syncthreads();
                }
            }
            gbar(tid, &gen);
        }
    }

    // ---- output ----
    for (int b = bid; b < BB; b += GRID) {
        if (tid < 128) {
            int s = g_seq[b * 32];
            const float4* src = reinterpret_cast<const float4*>(g_h + (size_t)(b * NS + s) * HH);
            reinterpret_cast<float4*>(out)[b * 128 + tid] = src[tid];
        }
    }
}

// ---------------- launch ----------------
extern "C" void kernel_launch(void* const* d_in, const int* in_sizes, int n_in,
                              void* d_out, int out_size)
{
    const float* x      = (const float*)d_in[0];
    const int*   length = (const int*)  d_in[1];
    const float* W_word = (const float*)d_in[2];
    const float* b_word = (const float*)d_in[3];
    const float* W_comp = (const float*)d_in[4];
    const float* b_comp = (const float*)d_in[5];
    const float* cq     = (const float*)d_in[6];
    float* out = (float*)d_out;

    persist_k<<<GRID, TPB>>>(x, length, W_word, b_word, W_comp, b_comp, cq, out);
}

// round 5
// speedup vs baseline: 2.1873x; 1.4447x over previous
#include <cuda_runtime.h>
#include <math.h>

#define BB   256
#define HH   512
#define DD   512
#define NS   64
#define G5   2560
#define GRID 148
#define TPB  512

// ---------------- static device scratch ----------------
__device__ float g_h [BB * NS * HH];
__device__ float g_c [BB * NS * HH];
__device__ float g_ch[BB * NS * HH];
__device__ float g_cc[BB * NS * HH];
__device__ float g_vl[(size_t)BB * NS * G5];
__device__ float g_vr[(size_t)BB * NS * G5];
__device__ float g_clog[BB * NS];
__device__ int   g_seq [BB * 32];
__device__ int4  g_jobs[BB * 2];
__device__ int   g_active[BB];
__device__ int   g_nact[32];
__device__ int   g_rowmap[BB * 32];
__device__ int   g_nrow;
__device__ int   g_bar_cnt = 0;
__device__ volatile int g_bar_gen = 0;

__device__ __forceinline__ float sigf(float x) { return 1.f / (1.f + expf(-x)); }

// ---------------- software grid barrier ----------------
__device__ __forceinline__ void gbar(int tid, int* gen)
{
    __syncthreads();
    if (tid == 0) {
        int target = *gen + 1;
        __threadfence();
        if (atomicAdd(&g_bar_cnt, 1) == GRID - 1) {
            g_bar_cnt = 0;
            __threadfence();
            g_bar_gen = target;
        } else {
            while (g_bar_gen - target < 0) __nanosleep(32);
            __threadfence();   // CCTL.IVALL: drop stale L1 lines
        }
        *gen = target;
    }
    __syncthreads();
}

// ---------------- big GEMM tile: 128x128, BK=16, 512 threads, microtile 8x4 ----
// mode 0: word proj   A = x[rowmap], B = W_word, +b_word -> g_h/g_c
// mode 1: leaf xform  A = g_h[rowmap slots], B = [Wl;Wr]  -> g_vl/g_vr
#define BIG_A(buf,k,r) sp[((buf)*16 + (k))*132 + (r)]
#define BIG_B(buf,k,r) sp[4224 + ((buf)*16 + (k))*132 + (r)]
__device__ void gemm_big(int mode, int m0, int n0, int NROW, int tid,
    float* __restrict__ sp, int* __restrict__ srow,
    const float* __restrict__ x, const float* __restrict__ Ww,
    const float* __restrict__ bw, const float* __restrict__ Wc)
{
    __syncthreads();
    if (tid < 128) {
        int r = m0 + tid;
        srow[tid] = (r < NROW) ? g_rowmap[r] : g_rowmap[0];
    }
    __syncthreads();

    const int lrow = tid >> 2;        // 0..127
    const int kq   = (tid & 3) * 4;   // 0,4,8,12

    const float* aptr;
    {
        int m = srow[lrow];
        aptr = (mode == 0) ? x + (size_t)m * DD + kq
                           : g_h + (size_t)(((m >> 5) << 6) + (m & 31)) * HH + kq;
    }
    const float* bptr;
    {
        int n = n0 + lrow;
        if (mode == 0) bptr = Ww + (size_t)n * DD + kq;
        else bptr = (n < G5) ? Wc + (size_t)n * 1024 + kq
                             : Wc + (size_t)(n - G5) * 1024 + 512 + kq;
    }

    const int ty = tid >> 5;   // warp id 0..15 -> rows ty*8 (smem broadcast)
    const int tx = tid & 31;   // lane -> cols tx*4

    float acc[8][4];
#pragma unroll
    for (int i = 0; i < 8; i++)
#pragma unroll
        for (int j = 0; j < 4; j++) acc[i][j] = 0.f;

    float4 ra = *reinterpret_cast<const float4*>(aptr);
    float4 rb = *reinterpret_cast<const float4*>(bptr);
    BIG_A(0, kq + 0, lrow) = ra.x; BIG_A(0, kq + 1, lrow) = ra.y;
    BIG_A(0, kq + 2, lrow) = ra.z; BIG_A(0, kq + 3, lrow) = ra.w;
    BIG_B(0, kq + 0, lrow) = rb.x; BIG_B(0, kq + 1, lrow) = rb.y;
    BIG_B(0, kq + 2, lrow) = rb.z; BIG_B(0, kq + 3, lrow) = rb.w;
    __syncthreads();

    int buf = 0;
    for (int k0 = 16; k0 <= 512; k0 += 16) {
        const bool more = (k0 < 512);
        if (more) {
            ra = *reinterpret_cast<const float4*>(aptr + k0);
            rb = *reinterpret_cast<const float4*>(bptr + k0);
        }
#pragma unroll
        for (int kk = 0; kk < 16; kk++) {
            float a[8], b[4];
            *reinterpret_cast<float4*>(a)     = *reinterpret_cast<const float4*>(&BIG_A(buf, kk, ty * 8));
            *reinterpret_cast<float4*>(a + 4) = *reinterpret_cast<const float4*>(&BIG_A(buf, kk, ty * 8 + 4));
            *reinterpret_cast<float4*>(b)     = *reinterpret_cast<const float4*>(&BIG_B(buf, kk, tx * 4));
#pragma unroll
            for (int i = 0; i < 8; i++)
#pragma unroll
                for (int j = 0; j < 4; j++)
                    acc[i][j] = fmaf(a[i], b[j], acc[i][j]);
        }
        if (more) {
            BIG_A(buf ^ 1, kq + 0, lrow) = ra.x; BIG_A(buf ^ 1, kq + 1, lrow) = ra.y;
            BIG_A(buf ^ 1, kq + 2, lrow) = ra.z; BIG_A(buf ^ 1, kq + 3, lrow) = ra.w;
            BIG_B(buf ^ 1, kq + 0, lrow) = rb.x; BIG_B(buf ^ 1, kq + 1, lrow) = rb.y;
            BIG_B(buf ^ 1, kq + 2, lrow) = rb.z; BIG_B(buf ^ 1, kq + 3, lrow) = rb.w;
        }
        __syncthreads();
        buf ^= 1;
    }

    const int nb = n0 + tx * 4;
    if (mode == 0) {
        float4 bi = *reinterpret_cast<const float4*>(&bw[nb]);
#pragma unroll
        for (int i = 0; i < 8; i++) {
            int r = ty * 8 + i;
            if (m0 + r < NROW) {
                int m = srow[r];
                int slot = ((m >> 5) << 6) + (m & 31);
                float* dst = (nb < HH) ? (g_h + (size_t)slot * HH + nb)
                                       : (g_c + (size_t)slot * HH + (nb - HH));
                *reinterpret_cast<float4*>(dst) =
                    make_float4(acc[i][0] + bi.x, acc[i][1] + bi.y,
                                acc[i][2] + bi.z, acc[i][3] + bi.w);
            }
        }
    } else {
#pragma unroll
        for (int i = 0; i < 8; i++) {
            int r = ty * 8 + i;
            if (m0 + r < NROW) {
                int m = srow[r];
                int slot = ((m >> 5) << 6) + (m & 31);
                size_t base = (size_t)slot * G5;
                float* dst = (nb < G5) ? (g_vl + base + nb) : (g_vr + base + (nb - G5));
                *reinterpret_cast<float4*>(dst) =
                    make_float4(acc[i][0], acc[i][1], acc[i][2], acc[i][3]);
            }
        }
    }
}

// ---------------- step GEMM half-tile: 64x64, BK=16, 256 threads, microtile 4x4 ----
// Both halves of the block MUST call this with identical trip counts (lockstep syncthreads).
#define ST_A(buf,k,r) hs[((buf)*16 + (k))*68 + (r)]
#define ST_B(buf,k,r) hs[2176 + ((buf)*16 + (k))*68 + (r)]
__device__ void gemm_step(int step, int nact, int m0, int n0, bool tvalid, int t,
    float* __restrict__ hs, const float* __restrict__ Wc)
{
    const int lrow = t >> 2;        // 0..63
    const int kq   = (t & 3) * 4;

    const float* aptr;
    {
        int m = m0 + lrow;
        int b = (tvalid && m < nact) ? g_active[m] : 0;
        aptr = g_h + (size_t)(b * NS + 32 + step) * HH + kq;
    }
    const float* bptr;
    {
        int n = tvalid ? (n0 + lrow) : lrow;
        bptr = (n < G5) ? Wc + (size_t)n * 1024 + kq
                        : Wc + (size_t)(n - G5) * 1024 + 512 + kq;
    }

    const int ty = t >> 4;   // rows ty*4
    const int tx = t & 15;   // cols tx*4

    float acc[4][4];
#pragma unroll
    for (int i = 0; i < 4; i++)
#pragma unroll
        for (int j = 0; j < 4; j++) acc[i][j] = 0.f;

    float4 ra = *reinterpret_cast<const float4*>(aptr);
    float4 rb = *reinterpret_cast<const float4*>(bptr);
    ST_A(0, kq + 0, lrow) = ra.x; ST_A(0, kq + 1, lrow) = ra.y;
    ST_A(0, kq + 2, lrow) = ra.z; ST_A(0, kq + 3, lrow) = ra.w;
    ST_B(0, kq + 0, lrow) = rb.x; ST_B(0, kq + 1, lrow) = rb.y;
    ST_B(0, kq + 2, lrow) = rb.z; ST_B(0, kq + 3, lrow) = rb.w;
    __syncthreads();

    int buf = 0;
    for (int k0 = 16; k0 <= 512; k0 += 16) {
        const bool more = (k0 < 512);
        if (more) {
            ra = *reinterpret_cast<const float4*>(aptr + k0);
            rb = *reinterpret_cast<const float4*>(bptr + k0);
        }
#pragma unroll
        for (int kk = 0; kk < 16; kk++) {
            float a[4], b[4];
            *reinterpret_cast<float4*>(a) = *reinterpret_cast<const float4*>(&ST_A(buf, kk, ty * 4));
            *reinterpret_cast<float4*>(b) = *reinterpret_cast<const float4*>(&ST_B(buf, kk, tx * 4));
#pragma unroll
            for (int i = 0; i < 4; i++)
#pragma unroll
                for (int j = 0; j < 4; j++)
                    acc[i][j] = fmaf(a[i], b[j], acc[i][j]);
        }
        if (more) {
            ST_A(buf ^ 1, kq + 0, lrow) = ra.x; ST_A(buf ^ 1, kq + 1, lrow) = ra.y;
            ST_A(buf ^ 1, kq + 2, lrow) = ra.z; ST_A(buf ^ 1, kq + 3, lrow) = ra.w;
            ST_B(buf ^ 1, kq + 0, lrow) = rb.x; ST_B(buf ^ 1, kq + 1, lrow) = rb.y;
            ST_B(buf ^ 1, kq + 2, lrow) = rb.z; ST_B(buf ^ 1, kq + 3, lrow) = rb.w;
        }
        __syncthreads();
        buf ^= 1;
    }

    if (tvalid) {
        const int nb = n0 + tx * 4;
#pragma unroll
        for (int i = 0; i < 4; i++) {
            int m = m0 + ty * 4 + i;
            if (m < nact) {
                int b = g_active[m];
                size_t base = (size_t)(b * NS + 32 + step) * G5;
                float* dst = (nb < G5) ? (g_vl + base + nb) : (g_vr + base + (nb - G5));
                *reinterpret_cast<float4*>(dst) = make_float4(acc[i][0], acc[i][1], acc[i][2], acc[i][3]);
            }
        }
    }
}

// ---------------- pair gates + partial logit (t2 in 0..127) ----------------
__device__ __forceinline__ float pair_body(int b, int key, int Ls, int Rs, int t,
    const float* __restrict__ b_comp, const float* __restrict__ cq)
{
    const float4* vl  = reinterpret_cast<const float4*>(g_vl + (size_t)(b * NS + Ls) * G5);
    const float4* vr  = reinterpret_cast<const float4*>(g_vr + (size_t)(b * NS + Rs) * G5);
    const float4* bc  = reinterpret_cast<const float4*>(b_comp);
    const float4* cl4 = reinterpret_cast<const float4*>(g_c + (size_t)(b * NS + Ls) * HH);
    const float4* cr4 = reinterpret_cast<const float4*>(g_c + (size_t)(b * NS + Rs) * HH);
    const float4* q4  = reinterpret_cast<const float4*>(cq);

    float vi[4], vfl[4], vfr[4], vu[4], vo[4];
    {
        float* dsts[5] = {vi, vfl, vfr, vu, vo};
#pragma unroll
        for (int g = 0; g < 5; g++) {
            float4 a  = vl[g * 128 + t];
            float4 bb = vr[g * 128 + t];
            float4 c  = bc[g * 128 + t];
            dsts[g][0] = a.x + bb.x + c.x;
            dsts[g][1] = a.y + bb.y + c.y;
            dsts[g][2] = a.z + bb.z + c.z;
            dsts[g][3] = a.w + bb.w + c.w;
        }
    }
    float4 cl = cl4[t], cr = cr4[t], qv = q4[t];
    float clv[4] = {cl.x, cl.y, cl.z, cl.w};
    float crv[4] = {cr.x, cr.y, cr.z, cr.w};
    float qa[4]  = {qv.x, qv.y, qv.z, qv.w};

    float hh[4], cc[4];
    float part = 0.f;
#pragma unroll
    for (int e = 0; e < 4; e++) {
        float c = clv[e] * sigf(vfl[e] + 1.f)
                + crv[e] * sigf(vfr[e] + 1.f)
                + tanhf(vu[e]) * sigf(vi[e]);
        float h = sigf(vo[e]) * tanhf(c);
        cc[e] = c; hh[e] = h;
        part = fmaf(qa[e], h, part);
    }
    reinterpret_cast<float4*>(g_ch + (size_t)(b * NS + key) * HH)[t] = make_float4(hh[0], hh[1], hh[2], hh[3]);
    reinterpret_cast<float4*>(g_cc + (size_t)(b * NS + key) * HH)[t] = make_float4(cc[0], cc[1], cc[2], cc[3]);
    return part;
}

// ---------------- plan for batch b at step i (one full warp, lane 0..31) --------
__device__ __forceinline__ void plan_do(int b, int i, int lane, const int* __restrict__ length)
{
    int ell = length[b];
    if (i + 1 < ell) {
        int npairs = 31 - i;
        int seqv = g_seq[b * 32 + lane];
        bool valid = (lane < ell - i - 1);
        float lg = valid ? g_clog[b * NS + seqv] : -1e9f;
        float mx = lg;
#pragma unroll
        for (int o = 16; o; o >>= 1) mx = fmaxf(mx, __shfl_xor_sync(0xffffffffu, mx, o));
        unsigned bal = __ballot_sync(0xffffffffu, lg == mx);
        int k = __ffs(bal) - 1;   // first-max = jnp.argmax

        int s    = 32 + i;
        int sk   = __shfl_sync(0xffffffffu, seqv, k);
        int skm1 = __shfl_sync(0xffffffffu, seqv, (k > 0) ? (k - 1) : 0);
        int skp2 = __shfl_sync(0xffffffffu, seqv, (k + 2 < 32) ? (k + 2) : 31);

        const float4* sh = reinterpret_cast<const float4*>(g_ch + (size_t)(b * NS + sk) * HH);
        const float4* sc = reinterpret_cast<const float4*>(g_cc + (size_t)(b * NS + sk) * HH);
        float4* dh = reinterpret_cast<float4*>(g_h + (size_t)(b * NS + s) * HH);
        float4* dc = reinterpret_cast<float4*>(g_c + (size_t)(b * NS + s) * HH);
#pragma unroll
        for (int r = 0; r < 4; r++) {
            dh[lane + 32 * r] = sh[lane + 32 * r];
            dc[lane + 32 * r] = sc[lane + 32 * r];
        }
        if (lane == 0) {
            int idx = atomicAdd(&g_nact[i], 1);
            g_active[idx] = b;
            g_jobs[b * 2]     = make_int4(skm1, skm1, s, (k >= 1) ? 1 : 0);
            g_jobs[b * 2 + 1] = make_int4(s, s, skp2, (k <= npairs - 2) ? 1 : 0);
        }
        int nxt = __shfl_down_sync(0xffffffffu, seqv, 1);
        int newv = (lane < k) ? seqv : ((lane == k) ? s : nxt);
        g_seq[b * 32 + lane] = newv;
    } else if (lane == 0) {
        g_jobs[b * 2]     = make_int4(0, 0, 0, 0);
        g_jobs[b * 2 + 1] = make_int4(0, 0, 0, 0);
    }
}

// ---------------- the persistent kernel ----------------
__global__ __launch_bounds__(TPB, 1) void persist_k(
    const float* __restrict__ x, const int* __restrict__ length,
    const float* __restrict__ W_word, const float* __restrict__ b_word,
    const float* __restrict__ W_comp, const float* __restrict__ b_comp,
    const float* __restrict__ cq, float* __restrict__ out)
{
    __shared__ __align__(16) float sp[8704];   // big: 2x(2x16x132); step: 2 halves x 2x(2x16x68)
    __shared__ int   srow[128];
    __shared__ float sws[16];

    const int tid  = threadIdx.x;
    const int bid  = blockIdx.x;
    const int half = tid >> 8;     // 0/1
    const int t256 = tid & 255;
    int gen = 0;
    if (tid == 0) gen = g_bar_gen;

    // ---- init: rowmap (block 0), seq (block 1), nact (block 2) ----
    if (bid == 0) {
        int* slen = (int*)sp;
        if (tid < BB) slen[tid] = length[tid];
        __syncthreads();
        if (tid < BB) {
            int s = 0;
            for (int q = 0; q < tid; q++) s += slen[q];
            int l = slen[tid];
            for (int k = 0; k < l; k++) g_rowmap[s + k] = tid * 32 + k;
            if (tid == BB - 1) g_nrow = s + l;
        }
    }
    if (bid == 1) {
        for (int idx = tid; idx < BB * 32; idx += TPB) g_seq[idx] = idx & 31;
    }
    if (bid == 2 && tid < 32) g_nact[tid] = 0;
    gbar(tid, &gen);

    const int NROW = g_nrow;
    const int MG   = (NROW + 127) >> 7;

    // ---- phase A: word projection over live rows ----
    for (int tt = bid; tt < MG * 8; tt += GRID)
        gemm_big(0, (tt >> 3) * 128, (tt & 7) * 128, NROW, tid, sp, srow, x, W_word, b_word, W_comp);
    gbar(tid, &gen);

    // ---- phase B: leaf transforms over live rows ----
    for (int tt = bid; tt < MG * 40; tt += GRID)
        gemm_big(1, (tt / 40) * 128, (tt % 40) * 128, NROW, tid, sp, srow, x, W_word, b_word, W_comp);
    gbar(tid, &gen);

    // ---- phase C: initial candidates (only pairs inside valid prefix) ----
    {
        const int grp = tid >> 7;     // 0..3
        const int t2  = tid & 127;
        const int w4  = (tid >> 5) & 3;
        for (int p = bid; p < 1984; p += GRID) {
            int j  = p * 4 + grp;
            int b  = j / 31;
            int jj = j - b * 31;
            bool valid = (jj + 1 < length[b]);
            float part = valid ? pair_body(b, jj, jj, jj + 1, t2, b_comp, cq) : 0.f;
#pragma unroll
            for (int o = 16; o; o >>= 1) part += __shfl_xor_sync(0xffffffffu, part, o);
            if ((t2 & 31) == 0) sws[grp * 4 + w4] = part;
            __syncthreads();
            if (t2 == 0 && valid) {
                float tot = sws[grp * 4] + sws[grp * 4 + 1] + sws[grp * 4 + 2] + sws[grp * 4 + 3];
                g_clog[b * NS + jj] = tot * 0.044194173824159216f;
            }
            __syncthreads();
        }
    }
    gbar(tid, &gen);

    // ---- plan(0): batch b on block b/2 (warp 0 of each half) ----
    {
        int b = bid * 2 + half;
        if (b < BB && t256 < 32) plan_do(b, 0, tid & 31, length);
    }
    gbar(tid, &gen);

    // ---- main loop ----
    for (int i = 0; i < 30; i++) {
        // step GEMM: dual 64x64 tiles per block (lockstep halves)
        {
            int nact  = g_nact[i];
            int ntile = ((nact + 63) >> 6) * 80;
            float* hs = sp + half * 4352;
            for (int tb = bid * 2; tb < ntile; tb += 2 * GRID) {
                int w = tb + half;
                bool tv = (w < ntile);
                int mgi = tv ? (w / 80) : 0;
                int ni  = tv ? (w % 80) : 0;
                gemm_step(i, nact, mgi * 64, ni * 64, tv, t256, hs, W_comp);
            }
        }
        gbar(tid, &gen);

        // PP: pair jobs of step i + plan(i+1), batch b on block b/2
        {
            int b = bid * 2 + half;
            bool bact = (b < BB);
            const int grp = tid >> 7;
            const int t2  = tid & 127;
            const int w4  = (tid >> 5) & 3;
            int4 job = make_int4(0, 0, 0, 0);
            if (bact) job = g_jobs[b * 2 + (t256 >> 7)];
            bool jact = bact && job.w;
            float part = jact ? pair_body(b, job.x, job.y, job.z, t2, b_comp, cq) : 0.f;
#pragma unroll
            for (int o = 16; o; o >>= 1) part += __shfl_xor_sync(0xffffffffu, part, o);
            if ((t2 & 31) == 0) sws[grp * 4 + w4] = part;
            __syncthreads();
            if (t2 == 0 && jact) {
                float tot = sws[grp * 4] + sws[grp * 4 + 1] + sws[grp * 4 + 2] + sws[grp * 4 + 3];
                g_clog[b * NS + job.x] = tot * 0.044194173824159216f;
            }
            __syncthreads();
            if (bact && t256 < 32) plan_do(b, i + 1, tid & 31, length);
        }
        gbar(tid, &gen);
    }

    // ---- output: h of root slot ----
    {
        int b = bid * 2 + half;
        if (b < BB && t256 < 128) {
            int s = g_seq[b * 32];
            const float4* src = reinterpret_cast<const float4*>(g_h + (size_t)(b * NS + s) * HH);
            reinterpret_cast<float4*>(out)[b * 128 + t256] = src[t256];
        }
    }
}

// ---------------- launch ----------------
extern "C" void kernel_launch(void* const* d_in, const int* in_sizes, int n_in,
                              void* d_out, int out_size)
{
    const float* x      = (const float*)d_in[0];
    const int*   length = (const int*)  d_in[1];
    const float* W_word = (const float*)d_in[2];
    const float* b_word = (const float*)d_in[3];
    const float* W_comp = (const float*)d_in[4];
    const float* b_comp = (const float*)d_in[5];
    const float* cq     = (const float*)d_in[6];
    float* out = (float*)d_out;

    persist_k<<<GRID, TPB>>>(x, length, W_word, b_word, W_comp, b_comp, cq, out);
}

// round 6
// speedup vs baseline: 2.2909x; 1.0474x over previous
#include <cuda_runtime.h>
#include <math.h>

#define BB   256
#define HH   512
#define DD   512
#define NS   64
#define G5   2560
#define GRID 148
#define TPB  512

// ---------------- static device scratch ----------------
__device__ float g_h [BB * NS * HH];
__device__ float g_c [BB * NS * HH];
__device__ float g_ch[BB * NS * HH];
__device__ float g_cc[BB * NS * HH];
__device__ float g_vl[(size_t)BB * NS * G5];
__device__ float g_vr[(size_t)BB * NS * G5];
__device__ float g_clog[BB * NS];
__device__ int   g_seq [BB * 32];
__device__ int4  g_jobs[BB * 2];
__device__ int   g_active[BB];
__device__ int   g_nact[32];
__device__ int   g_rowmap[BB * 32];
__device__ int   g_nrow;
__device__ int   g_bar_cnt = 0;
__device__ volatile int g_bar_gen = 0;

__device__ __forceinline__ float sigf(float x) { return 1.f / (1.f + expf(-x)); }

// ---------------- software grid barrier ----------------
__device__ __forceinline__ void gbar(int tid, int* gen)
{
    __syncthreads();
    if (tid == 0) {
        int target = *gen + 1;
        __threadfence();
        if (atomicAdd(&g_bar_cnt, 1) == GRID - 1) {
            g_bar_cnt = 0;
            __threadfence();
            g_bar_gen = target;
        } else {
            while (g_bar_gen - target < 0) __nanosleep(32);
            __threadfence();   // CCTL.IVALL: drop stale L1 lines
        }
        *gen = target;
    }
    __syncthreads();
}

// ---------------- big GEMM tile: 128x128, BK=16, 512 threads, microtile 8x4 ----
// mode 0: word proj   A = x[rowmap], B = W_word, +b_word -> g_h/g_c
// mode 1: leaf xform  A = g_h[rowmap slots], B = [Wl;Wr]  -> g_vl/g_vr
#define BIG_A(buf,k,r) sp[((buf)*16 + (k))*132 + (r)]
#define BIG_B(buf,k,r) sp[4224 + ((buf)*16 + (k))*132 + (r)]
__device__ void gemm_big(int mode, int m0, int n0, int NROW, int tid,
    float* __restrict__ sp, int* __restrict__ srow,
    const float* __restrict__ x, const float* __restrict__ Ww,
    const float* __restrict__ bw, const float* __restrict__ Wc)
{
    __syncthreads();
    if (tid < 128) {
        int r = m0 + tid;
        srow[tid] = (r < NROW) ? g_rowmap[r] : g_rowmap[0];
    }
    __syncthreads();

    const int lrow = tid >> 2;        // 0..127
    const int kq   = (tid & 3) * 4;   // 0,4,8,12

    const float* aptr;
    {
        int m = srow[lrow];
        aptr = (mode == 0) ? x + (size_t)m * DD + kq
                           : g_h + (size_t)(((m >> 5) << 6) + (m & 31)) * HH + kq;
    }
    const float* bptr;
    {
        int n = n0 + lrow;
        if (mode == 0) bptr = Ww + (size_t)n * DD + kq;
        else bptr = (n < G5) ? Wc + (size_t)n * 1024 + kq
                             : Wc + (size_t)(n - G5) * 1024 + 512 + kq;
    }

    const int ty = tid >> 5;   // warp id 0..15 -> rows ty*8 (smem broadcast)
    const int tx = tid & 31;   // lane -> cols tx*4

    float acc[8][4];
#pragma unroll
    for (int i = 0; i < 8; i++)
#pragma unroll
        for (int j = 0; j < 4; j++) acc[i][j] = 0.f;

    float4 ra = *reinterpret_cast<const float4*>(aptr);
    float4 rb = *reinterpret_cast<const float4*>(bptr);
    BIG_A(0, kq + 0, lrow) = ra.x; BIG_A(0, kq + 1, lrow) = ra.y;
    BIG_A(0, kq + 2, lrow) = ra.z; BIG_A(0, kq + 3, lrow) = ra.w;
    BIG_B(0, kq + 0, lrow) = rb.x; BIG_B(0, kq + 1, lrow) = rb.y;
    BIG_B(0, kq + 2, lrow) = rb.z; BIG_B(0, kq + 3, lrow) = rb.w;
    __syncthreads();

    int buf = 0;
    for (int k0 = 16; k0 <= 512; k0 += 16) {
        const bool more = (k0 < 512);
        if (more) {
            ra = *reinterpret_cast<const float4*>(aptr + k0);
            rb = *reinterpret_cast<const float4*>(bptr + k0);
        }
#pragma unroll
        for (int kk = 0; kk < 16; kk++) {
            float a[8], b[4];
            *reinterpret_cast<float4*>(a)     = *reinterpret_cast<const float4*>(&BIG_A(buf, kk, ty * 8));
            *reinterpret_cast<float4*>(a + 4) = *reinterpret_cast<const float4*>(&BIG_A(buf, kk, ty * 8 + 4));
            *reinterpret_cast<float4*>(b)     = *reinterpret_cast<const float4*>(&BIG_B(buf, kk, tx * 4));
#pragma unroll
            for (int i = 0; i < 8; i++)
#pragma unroll
                for (int j = 0; j < 4; j++)
                    acc[i][j] = fmaf(a[i], b[j], acc[i][j]);
        }
        if (more) {
            BIG_A(buf ^ 1, kq + 0, lrow) = ra.x; BIG_A(buf ^ 1, kq + 1, lrow) = ra.y;
            BIG_A(buf ^ 1, kq + 2, lrow) = ra.z; BIG_A(buf ^ 1, kq + 3, lrow) = ra.w;
            BIG_B(buf ^ 1, kq + 0, lrow) = rb.x; BIG_B(buf ^ 1, kq + 1, lrow) = rb.y;
            BIG_B(buf ^ 1, kq + 2, lrow) = rb.z; BIG_B(buf ^ 1, kq + 3, lrow) = rb.w;
        }
        __syncthreads();
        buf ^= 1;
    }

    const int nb = n0 + tx * 4;
    if (mode == 0) {
        float4 bi = *reinterpret_cast<const float4*>(&bw[nb]);
#pragma unroll
        for (int i = 0; i < 8; i++) {
            int r = ty * 8 + i;
            if (m0 + r < NROW) {
                int m = srow[r];
                int slot = ((m >> 5) << 6) + (m & 31);
                float* dst = (nb < HH) ? (g_h + (size_t)slot * HH + nb)
                                       : (g_c + (size_t)slot * HH + (nb - HH));
                *reinterpret_cast<float4*>(dst) =
                    make_float4(acc[i][0] + bi.x, acc[i][1] + bi.y,
                                acc[i][2] + bi.z, acc[i][3] + bi.w);
            }
        }
    } else {
#pragma unroll
        for (int i = 0; i < 8; i++) {
            int r = ty * 8 + i;
            if (m0 + r < NROW) {
                int m = srow[r];
                int slot = ((m >> 5) << 6) + (m & 31);
                size_t base = (size_t)slot * G5;
                float* dst = (nb < G5) ? (g_vl + base + nb) : (g_vr + base + (nb - G5));
                *reinterpret_cast<float4*>(dst) =
                    make_float4(acc[i][0], acc[i][1], acc[i][2], acc[i][3]);
            }
        }
    }
}

// ---------------- step GEMM half-tile: 64x64, BK=16, 256 threads, microtile 4x4 ----
// Both halves of the block MUST call this with identical trip counts (lockstep syncthreads).
#define ST_A(buf,k,r) hs[((buf)*16 + (k))*68 + (r)]
#define ST_B(buf,k,r) hs[2176 + ((buf)*16 + (k))*68 + (r)]
__device__ void gemm_step(int step, int nact, int m0, int n0, bool tvalid, int t,
    float* __restrict__ hs, const float* __restrict__ Wc)
{
    const int lrow = t >> 2;        // 0..63
    const int kq   = (t & 3) * 4;

    const float* aptr;
    {
        int m = m0 + lrow;
        int b = (tvalid && m < nact) ? g_active[m] : 0;
        aptr = g_h + (size_t)(b * NS + 32 + step) * HH + kq;
    }
    const float* bptr;
    {
        int n = tvalid ? (n0 + lrow) : lrow;
        bptr = (n < G5) ? Wc + (size_t)n * 1024 + kq
                        : Wc + (size_t)(n - G5) * 1024 + 512 + kq;
    }

    const int ty = t >> 4;   // rows ty*4
    const int tx = t & 15;   // cols tx*4

    float acc[4][4];
#pragma unroll
    for (int i = 0; i < 4; i++)
#pragma unroll
        for (int j = 0; j < 4; j++) acc[i][j] = 0.f;

    float4 ra = *reinterpret_cast<const float4*>(aptr);
    float4 rb = *reinterpret_cast<const float4*>(bptr);
    ST_A(0, kq + 0, lrow) = ra.x; ST_A(0, kq + 1, lrow) = ra.y;
    ST_A(0, kq + 2, lrow) = ra.z; ST_A(0, kq + 3, lrow) = ra.w;
    ST_B(0, kq + 0, lrow) = rb.x; ST_B(0, kq + 1, lrow) = rb.y;
    ST_B(0, kq + 2, lrow) = rb.z; ST_B(0, kq + 3, lrow) = rb.w;
    __syncthreads();

    int buf = 0;
    for (int k0 = 16; k0 <= 512; k0 += 16) {
        const bool more = (k0 < 512);
        if (more) {
            ra = *reinterpret_cast<const float4*>(aptr + k0);
            rb = *reinterpret_cast<const float4*>(bptr + k0);
        }
#pragma unroll
        for (int kk = 0; kk < 16; kk++) {
            float a[4], b[4];
            *reinterpret_cast<float4*>(a) = *reinterpret_cast<const float4*>(&ST_A(buf, kk, ty * 4));
            *reinterpret_cast<float4*>(b) = *reinterpret_cast<const float4*>(&ST_B(buf, kk, tx * 4));
#pragma unroll
            for (int i = 0; i < 4; i++)
#pragma unroll
                for (int j = 0; j < 4; j++)
                    acc[i][j] = fmaf(a[i], b[j], acc[i][j]);
        }
        if (more) {
            ST_A(buf ^ 1, kq + 0, lrow) = ra.x; ST_A(buf ^ 1, kq + 1, lrow) = ra.y;
            ST_A(buf ^ 1, kq + 2, lrow) = ra.z; ST_A(buf ^ 1, kq + 3, lrow) = ra.w;
            ST_B(buf ^ 1, kq + 0, lrow) = rb.x; ST_B(buf ^ 1, kq + 1, lrow) = rb.y;
            ST_B(buf ^ 1, kq + 2, lrow) = rb.z; ST_B(buf ^ 1, kq + 3, lrow) = rb.w;
        }
        __syncthreads();
        buf ^= 1;
    }

    if (tvalid) {
        const int nb = n0 + tx * 4;
#pragma unroll
        for (int i = 0; i < 4; i++) {
            int m = m0 + ty * 4 + i;
            if (m < nact) {
                int b = g_active[m];
                size_t base = (size_t)(b * NS + 32 + step) * G5;
                float* dst = (nb < G5) ? (g_vl + base + nb) : (g_vr + base + (nb - G5));
                *reinterpret_cast<float4*>(dst) = make_float4(acc[i][0], acc[i][1], acc[i][2], acc[i][3]);
            }
        }
    }
}

// ---------------- pair gates + partial logit (t2 in 0..127) ----------------
__device__ __forceinline__ float pair_body(int b, int key, int Ls, int Rs, int t,
    const float* __restrict__ b_comp, const float* __restrict__ cq)
{
    const float4* vl  = reinterpret_cast<const float4*>(g_vl + (size_t)(b * NS + Ls) * G5);
    const float4* vr  = reinterpret_cast<const float4*>(g_vr + (size_t)(b * NS + Rs) * G5);
    const float4* bc  = reinterpret_cast<const float4*>(b_comp);
    const float4* cl4 = reinterpret_cast<const float4*>(g_c + (size_t)(b * NS + Ls) * HH);
    const float4* cr4 = reinterpret_cast<const float4*>(g_c + (size_t)(b * NS + Rs) * HH);
    const float4* q4  = reinterpret_cast<const float4*>(cq);

    float vi[4], vfl[4], vfr[4], vu[4], vo[4];
    {
        float* dsts[5] = {vi, vfl, vfr, vu, vo};
#pragma unroll
        for (int g = 0; g < 5; g++) {
            float4 a  = vl[g * 128 + t];
            float4 bb = vr[g * 128 + t];
            float4 c  = bc[g * 128 + t];
            dsts[g][0] = a.x + bb.x + c.x;
            dsts[g][1] = a.y + bb.y + c.y;
            dsts[g][2] = a.z + bb.z + c.z;
            dsts[g][3] = a.w + bb.w + c.w;
        }
    }
    float4 cl = cl4[t], cr = cr4[t], qv = q4[t];
    float clv[4] = {cl.x, cl.y, cl.z, cl.w};
    float crv[4] = {cr.x, cr.y, cr.z, cr.w};
    float qa[4]  = {qv.x, qv.y, qv.z, qv.w};

    float hh[4], cc[4];
    float part = 0.f;
#pragma unroll
    for (int e = 0; e < 4; e++) {
        float c = clv[e] * sigf(vfl[e] + 1.f)
                + crv[e] * sigf(vfr[e] + 1.f)
                + tanhf(vu[e]) * sigf(vi[e]);
        float h = sigf(vo[e]) * tanhf(c);
        cc[e] = c; hh[e] = h;
        part = fmaf(qa[e], h, part);
    }
    reinterpret_cast<float4*>(g_ch + (size_t)(b * NS + key) * HH)[t] = make_float4(hh[0], hh[1], hh[2], hh[3]);
    reinterpret_cast<float4*>(g_cc + (size_t)(b * NS + key) * HH)[t] = make_float4(cc[0], cc[1], cc[2], cc[3]);
    return part;
}

// ---------------- plan for batch b at step i (one full warp, lane 0..31) --------
__device__ __forceinline__ void plan_do(int b, int i, int lane, const int* __restrict__ length)
{
    int ell = length[b];
    if (i + 1 < ell) {
        int npairs = 31 - i;
        int seqv = g_seq[b * 32 + lane];
        bool valid = (lane < ell - i - 1);
        float lg = valid ? g_clog[b * NS + seqv] : -1e9f;
        float mx = lg;
#pragma unroll
        for (int o = 16; o; o >>= 1) mx = fmaxf(mx, __shfl_xor_sync(0xffffffffu, mx, o));
        unsigned bal = __ballot_sync(0xffffffffu, lg == mx);
        int k = __ffs(bal) - 1;   // first-max = jnp.argmax

        int s    = 32 + i;
        int sk   = __shfl_sync(0xffffffffu, seqv, k);
        int skm1 = __shfl_sync(0xffffffffu, seqv, (k > 0) ? (k - 1) : 0);
        int skp2 = __shfl_sync(0xffffffffu, seqv, (k + 2 < 32) ? (k + 2) : 31);

        const float4* sh = reinterpret_cast<const float4*>(g_ch + (size_t)(b * NS + sk) * HH);
        const float4* sc = reinterpret_cast<const float4*>(g_cc + (size_t)(b * NS + sk) * HH);
        float4* dh = reinterpret_cast<float4*>(g_h + (size_t)(b * NS + s) * HH);
        float4* dc = reinterpret_cast<float4*>(g_c + (size_t)(b * NS + s) * HH);
#pragma unroll
        for (int r = 0; r < 4; r++) {
            dh[lane + 32 * r] = sh[lane + 32 * r];
            dc[lane + 32 * r] = sc[lane + 32 * r];
        }
        if (lane == 0) {
            int idx = atomicAdd(&g_nact[i], 1);
            g_active[idx] = b;
            g_jobs[b * 2]     = make_int4(skm1, skm1, s, (k >= 1) ? 1 : 0);
            g_jobs[b * 2 + 1] = make_int4(s, s, skp2, (k <= npairs - 2) ? 1 : 0);
        }
        int nxt = __shfl_down_sync(0xffffffffu, seqv, 1);
        int newv = (lane < k) ? seqv : ((lane == k) ? s : nxt);
        g_seq[b * 32 + lane] = newv;
    } else if (lane == 0) {
        g_jobs[b * 2]     = make_int4(0, 0, 0, 0);
        g_jobs[b * 2 + 1] = make_int4(0, 0, 0, 0);
    }
}

// ---------------- the persistent kernel ----------------
__global__ __launch_bounds__(TPB, 1) void persist_k(
    const float* __restrict__ x, const int* __restrict__ length,
    const float* __restrict__ W_word, const float* __restrict__ b_word,
    const float* __restrict__ W_comp, const float* __restrict__ b_comp,
    const float* __restrict__ cq, float* __restrict__ out)
{
    __shared__ __align__(16) float sp[8704];   // big: 2x(2x16x132); step: 2 halves x 2x(2x16x68)
    __shared__ int   srow[128];
    __shared__ float sws[16];

    const int tid  = threadIdx.x;
    const int bid  = blockIdx.x;
    const int half = tid >> 8;     // 0/1
    const int t256 = tid & 255;
    int gen = 0;
    if (tid == 0) gen = g_bar_gen;

    // ---- init: rowmap (block 0), seq (block 1), nact (block 2) ----
    if (bid == 0) {
        int* slen = (int*)sp;
        if (tid < BB) slen[tid] = length[tid];
        __syncthreads();
        if (tid < BB) {
            int s = 0;
            for (int q = 0; q < tid; q++) s += slen[q];
            int l = slen[tid];
            for (int k = 0; k < l; k++) g_rowmap[s + k] = tid * 32 + k;
            if (tid == BB - 1) g_nrow = s + l;
        }
    }
    if (bid == 1) {
        for (int idx = tid; idx < BB * 32; idx += TPB) g_seq[idx] = idx & 31;
    }
    if (bid == 2 && tid < 32) g_nact[tid] = 0;
    gbar(tid, &gen);

    const int NROW = g_nrow;
    const int MG   = (NROW + 127) >> 7;

    // ---- phase A: word projection over live rows ----
    for (int tt = bid; tt < MG * 8; tt += GRID)
        gemm_big(0, (tt >> 3) * 128, (tt & 7) * 128, NROW, tid, sp, srow, x, W_word, b_word, W_comp);
    gbar(tid, &gen);

    // ---- phase B: leaf transforms over live rows ----
    for (int tt = bid; tt < MG * 40; tt += GRID)
        gemm_big(1, (tt / 40) * 128, (tt % 40) * 128, NROW, tid, sp, srow, x, W_word, b_word, W_comp);
    gbar(tid, &gen);

    // ---- phase C: initial candidates (only pairs inside valid prefix) ----
    {
        const int grp = tid >> 7;     // 0..3
        const int t2  = tid & 127;
        const int w4  = (tid >> 5) & 3;
        for (int p = bid; p < 1984; p += GRID) {
            int j  = p * 4 + grp;
            int b  = j / 31;
            int jj = j - b * 31;
            bool valid = (jj + 1 < length[b]);
            float part = valid ? pair_body(b, jj, jj, jj + 1, t2, b_comp, cq) : 0.f;
#pragma unroll
            for (int o = 16; o; o >>= 1) part += __shfl_xor_sync(0xffffffffu, part, o);
            if ((t2 & 31) == 0) sws[grp * 4 + w4] = part;
            __syncthreads();
            if (t2 == 0 && valid) {
                float tot = sws[grp * 4] + sws[grp * 4 + 1] + sws[grp * 4 + 2] + sws[grp * 4 + 3];
                g_clog[b * NS + jj] = tot * 0.044194173824159216f;
            }
            __syncthreads();
        }
    }
    gbar(tid, &gen);

    // ---- plan(0): batch b on block b/2 (warp 0 of each half) ----
    {
        int b = bid * 2 + half;
        if (b < BB && t256 < 32) plan_do(b, 0, tid & 31, length);
    }
    gbar(tid, &gen);

    // ---- main loop ----
    for (int i = 0; i < 30; i++) {
        // step GEMM: dual 64x64 tiles per block (lockstep halves)
        {
            int nact  = g_nact[i];
            int ntile = ((nact + 63) >> 6) * 80;
            float* hs = sp + half * 4352;
            for (int tb = bid * 2; tb < ntile; tb += 2 * GRID) {
                int w = tb + half;
                bool tv = (w < ntile);
                int mgi = tv ? (w / 80) : 0;
                int ni  = tv ? (w % 80) : 0;
                gemm_step(i, nact, mgi * 64, ni * 64, tv, t256, hs, W_comp);
            }
        }
        gbar(tid, &gen);

        // PP: pair jobs of step i + plan(i+1), batch b on block b/2
        {
            int b = bid * 2 + half;
            bool bact = (b < BB);
            const int grp = tid >> 7;
            const int t2  = tid & 127;
            const int w4  = (tid >> 5) & 3;
            int4 job = make_int4(0, 0, 0, 0);
            if (bact) job = g_jobs[b * 2 + (t256 >> 7)];
            bool jact = bact && job.w;
            float part = jact ? pair_body(b, job.x, job.y, job.z, t2, b_comp, cq) : 0.f;
#pragma unroll
            for (int o = 16; o; o >>= 1) part += __shfl_xor_sync(0xffffffffu, part, o);
            if ((t2 & 31) == 0) sws[grp * 4 + w4] = part;
            __syncthreads();
            if (t2 == 0 && jact) {
                float tot = sws[grp * 4] + sws[grp * 4 + 1] + sws[grp * 4 + 2] + sws[grp * 4 + 3];
                g_clog[b * NS + job.x] = tot * 0.044194173824159216f;
            }
            __syncthreads();
            if (bact && t256 < 32) plan_do(b, i + 1, tid & 31, length);
        }
        gbar(tid, &gen);
    }

    // ---- output: h of root slot ----
    {
        int b = bid * 2 + half;
        if (b < BB && t256 < 128) {
            int s = g_seq[b * 32];
            const float4* src = reinterpret_cast<const float4*>(g_h + (size_t)(b * NS + s) * HH);
            reinterpret_cast<float4*>(out)[b * 128 + t256] = src[t256];
        }
    }
}

// ---------------- launch ----------------
extern "C" void kernel_launch(void* const* d_in, const int* in_sizes, int n_in,
                              void* d_out, int out_size)
{
    const float* x      = (const float*)d_in[0];
    const int*   length = (const int*)  d_in[1];
    const float* W_word = (const float*)d_in[2];
    const float* b_word = (const float*)d_in[3];
    const float* W_comp = (const float*)d_in[4];
    const float* b_comp = (const float*)d_in[5];
    const float* cq     = (const float*)d_in[6];
    float* out = (float*)d_out;

    persist_k<<<GRID, TPB>>>(x, length, W_word, b_word, W_comp, b_comp, cq, out);
}